// round 5
// baseline (speedup 1.0000x reference)
#include <cuda_runtime.h>
#include <cuda_bf16.h>

#define B_  8
#define C_  256
#define P_  1024
#define T_  16
#define DT  512      // D*T
#define PT  16384    // P*T
#define BH  64

// Scratch
__device__ __nv_bfloat16 g_K[(size_t)BH * P_ * DT];  // [bh][p][dt] bf16
__device__ __nv_bfloat16 g_Q[(size_t)BH * P_ * DT];  // [bh][p][dt] bf16
__device__ float g_V[(size_t)BH * P_ * DT];          // [bh][p][perm32(dt)] tf32-rounded
__device__ float g_E[(size_t)BH * P_ * P_];          // [bh][p][permq16(q)]

#define SA 36     // proj row-k stride (words)
#define ST 136    // k-major stride (words)
#define SEW 20    // energy bf16 row stride (32-bit words)
#define NTHR 256

__device__ __forceinline__ unsigned f2tf(float f) {
    unsigned u; asm("cvt.rna.tf32.f32 %0, %1;" : "=r"(u) : "f"(f)); return u;
}
__device__ __forceinline__ float rtf(float f) { return __uint_as_float(f2tf(f)); }

__device__ __forceinline__ void mma8(float* c, unsigned a0, unsigned a1, unsigned a2, unsigned a3,
                                     unsigned b0, unsigned b1) {
    asm volatile(
        "mma.sync.aligned.m16n8k8.row.col.f32.tf32.tf32.f32 "
        "{%0,%1,%2,%3},{%4,%5,%6,%7},{%8,%9},{%0,%1,%2,%3};"
        : "+f"(c[0]), "+f"(c[1]), "+f"(c[2]), "+f"(c[3])
        : "r"(a0), "r"(a1), "r"(a2), "r"(a3), "r"(b0), "r"(b1));
}
__device__ __forceinline__ void mmabf(float* c, unsigned a0, unsigned a1, unsigned a2, unsigned a3,
                                      unsigned b0, unsigned b1) {
    asm volatile(
        "mma.sync.aligned.m16n8k16.row.col.f32.bf16.bf16.f32 "
        "{%0,%1,%2,%3},{%4,%5,%6,%7},{%8,%9},{%0,%1,%2,%3};"
        : "+f"(c[0]), "+f"(c[1]), "+f"(c[2]), "+f"(c[3])
        : "r"(a0), "r"(a1), "r"(a2), "r"(a3), "r"(b0), "r"(b1));
}
__device__ __forceinline__ void cp16(void* s, const void* g) {
    unsigned a = (unsigned)__cvta_generic_to_shared(s);
    asm volatile("cp.async.cg.shared.global [%0], [%1], 16;" :: "r"(a), "l"(g));
}
__device__ __forceinline__ void cpc()  { asm volatile("cp.async.commit_group;"); }
__device__ __forceinline__ void cpw1() { asm volatile("cp.async.wait_group 1;"); }

// ---- tile loaders ----
__device__ __forceinline__ void load_rk(float* buf, const float* g, int ldg, int tid) {
#pragma unroll
    for (int j = 0; j < 4; j++) {
        int c = tid + j * NTHR;
        int row = c >> 3, col = (c & 7) * 4;
        cp16(buf + row * SA + col, g + (size_t)row * ldg + col);
    }
}
__device__ __forceinline__ void load_t(float* buf, const float* g, int ldg, int tid) {
#pragma unroll
    for (int j = 0; j < 4; j++) {
        int c = tid + j * NTHR;
        int row = c >> 5, col = (c & 31) * 4;
        cp16(buf + row * ST + col, g + (size_t)row * ldg + col);
    }
}
// energy: 128 rows x 32 bf16 (64B/row = 4 x 16B), stride SEW words
__device__ __forceinline__ void load_ebf(unsigned* buf, const __nv_bfloat16* g, int tid) {
#pragma unroll
    for (int j = 0; j < 2; j++) {
        int c = tid + j * NTHR;
        int row = c >> 2, ch = c & 3;
        cp16(buf + row * SEW + ch * 4, g + (size_t)row * DT + ch * 8);
    }
}

// ---- proj compute: A row-k (cvt), B k-major (cvt), tf32 ----
__device__ __forceinline__ void comp_rk_t(const float* As, const float* Bt, float acc[4][4][4],
                                          int wm, int wn, int g, int tig) {
#pragma unroll
    for (int kk = 0; kk < 4; kk++) {
        int k0 = kk * 8 + tig;
        unsigned a[4][4];
#pragma unroll
        for (int mi = 0; mi < 4; mi++) {
            int r = wm * 64 + mi * 16 + g;
            a[mi][0] = f2tf(As[r * SA + k0]);       a[mi][1] = f2tf(As[(r + 8) * SA + k0]);
            a[mi][2] = f2tf(As[r * SA + k0 + 4]);   a[mi][3] = f2tf(As[(r + 8) * SA + k0 + 4]);
        }
#pragma unroll
        for (int ni = 0; ni < 4; ni++) {
            int n = wn * 32 + ni * 8 + g;
            unsigned b0 = f2tf(Bt[k0 * ST + n]), b1 = f2tf(Bt[(k0 + 4) * ST + n]);
#pragma unroll
            for (int mi = 0; mi < 4; mi++)
                mma8(acc[mi][ni], a[mi][0], a[mi][1], a[mi][2], a[mi][3], b0, b1);
        }
    }
}

// ---- energy compute: bf16 k16, both operands row-k [row][k/2 words], stride SEW ----
__device__ __forceinline__ void comp_ebf(const unsigned* As, const unsigned* Bs, float acc[4][4][4],
                                         int wm, int wn, int g, int tig) {
#pragma unroll
    for (int c = 0; c < 2; c++) {
        int w0 = c * 8 + tig;
        unsigned b[4][2];
#pragma unroll
        for (int ni = 0; ni < 4; ni++) {
            int rn = wn * 32 + ni * 8 + g;
            b[ni][0] = Bs[rn * SEW + w0]; b[ni][1] = Bs[rn * SEW + w0 + 4];
        }
#pragma unroll
        for (int mi = 0; mi < 4; mi++) {
            int r = wm * 64 + mi * 16 + g;
            unsigned a0 = As[r * SEW + w0],     a1 = As[(r + 8) * SEW + w0];
            unsigned a2 = As[r * SEW + w0 + 4], a3 = As[(r + 8) * SEW + w0 + 4];
#pragma unroll
            for (int ni = 0; ni < 4; ni++)
                mmabf(acc[mi][ni], a0, a1, a2, a3, b[ni][0], b[ni][1]);
        }
    }
}

// ---- av compute: A k-major (q pair-perm, LDS.64), B k-major (col-perm, LDS.128), tf32 ----
__device__ __forceinline__ void comp_av(const float* At, const float* Bt, float acc[4][4][4],
                                        int wm, int wn, int g, int tig) {
#pragma unroll
    for (int kk = 0; kk < 4; kk++) {
        int k0 = kk * 8 + tig;
        float4 vb0 = *(const float4*)(Bt + k0 * ST + wn * 32 + 4 * g);
        float4 vb1 = *(const float4*)(Bt + (k0 + 4) * ST + wn * 32 + 4 * g);
        const float* b0p = &vb0.x;
        const float* b1p = &vb1.x;
#pragma unroll
        for (int mi = 0; mi < 4; mi++) {
            int cb = wm * 64 + mi * 16 + 2 * g;
            float2 lo = *(const float2*)(At + k0 * ST + cb);
            float2 hi = *(const float2*)(At + (k0 + 4) * ST + cb);
            unsigned a0 = __float_as_uint(lo.x), a1 = __float_as_uint(lo.y);
            unsigned a2 = __float_as_uint(hi.x), a3 = __float_as_uint(hi.y);
#pragma unroll
            for (int ni = 0; ni < 4; ni++)
                mma8(acc[mi][ni], a0, a1, a2, a3,
                     __float_as_uint(b0p[ni]), __float_as_uint(b1p[ni]));
        }
    }
}

#define ZERO_ACC(acc) \
    _Pragma("unroll") for (int mi = 0; mi < 4; mi++) \
    _Pragma("unroll") for (int ni = 0; ni < 4; ni++) \
    _Pragma("unroll") for (int e = 0; e < 4; e++) acc[mi][ni][e] = 0.f;

// ---------------------------------------------------------------------------
// proj: Y[o, pt] = sum_c W[o,c] x[b,c,pt]
// K,Q -> bf16 [p][dt]; V -> fp32 tf32-rounded [p][perm32(dt)]
// ---------------------------------------------------------------------------
__global__ __launch_bounds__(256) void proj_kernel(const float* __restrict__ x,
                                                   const float* __restrict__ Wk,
                                                   const float* __restrict__ Wq,
                                                   const float* __restrict__ Wv) {
    extern __shared__ float sm[];
    const int STG = 4608 + 4352;
    int tid = threadIdx.x, lane = tid & 31, warp = tid >> 5;
    int g = lane >> 2, tig = lane & 3, wm = warp >> 2, wn = warp & 3;
    int bz = blockIdx.z, w = bz % 3, b = bz / 3;
    const float* W = (w == 0) ? Wk : (w == 1) ? Wq : Wv;
    int m0 = blockIdx.y * 128, n0 = blockIdx.x * 128;
    const float* Ap = W + (size_t)m0 * C_;
    const float* Bp = x + (size_t)b * C_ * PT + n0;

    float acc[4][4][4]; ZERO_ACC(acc);
    const int NIT = C_ / 32;
    load_rk(sm, Ap, C_, tid);            load_t(sm + 4608, Bp, PT, tid);            cpc();
    load_rk(sm + STG, Ap + 32, C_, tid); load_t(sm + STG + 4608, Bp + 32 * PT, PT, tid); cpc();
    int sc = 0, sl = 2;
    for (int i = 0; i < NIT; i++) {
        cpw1(); __syncthreads();
        if (i + 2 < NIT) {
            load_rk(sm + sl * STG, Ap + (i + 2) * 32, C_, tid);
            load_t(sm + sl * STG + 4608, Bp + (size_t)(i + 2) * 32 * PT, PT, tid);
        }
        cpc();
        comp_rk_t(sm + sc * STG, sm + sc * STG + 4608, acc, wm, wn, g, tig);
        sc = (sc == 2) ? 0 : sc + 1; sl = (sl == 2) ? 0 : sl + 1;
    }

    if (w == 2) {
        // V: fp32, column-permuted within dt-32 groups
#pragma unroll
        for (int mi = 0; mi < 4; mi++)
#pragma unroll
            for (int half = 0; half < 2; half++) {
                int o = m0 + wm * 64 + mi * 16 + g + half * 8;
                int h = o >> 5, d = o & 31;
                size_t base = ((size_t)(b * 8 + h)) * P_;
#pragma unroll
                for (int ni = 0; ni < 4; ni++)
#pragma unroll
                    for (int e = 0; e < 2; e++) {
                        int col = n0 + wn * 32 + ni * 8 + 2 * tig + e;
                        int p = col >> 4, t = col & 15;
                        int dt = d * 16 + t;
                        int dtp = (dt & ~31) | (4 * (dt & 7) + ((dt >> 3) & 3));
                        g_V[(base + p) * DT + dtp] = rtf(acc[mi][ni][2 * half + e]);
                    }
            }
    } else {
        __nv_bfloat16* dst = (w == 0) ? g_K : g_Q;
#pragma unroll
        for (int mi = 0; mi < 4; mi++)
#pragma unroll
            for (int half = 0; half < 2; half++) {
                int o = m0 + wm * 64 + mi * 16 + g + half * 8;
                int h = o >> 5, d = o & 31;
                size_t base = ((size_t)(b * 8 + h)) * P_;
#pragma unroll
                for (int ni = 0; ni < 4; ni++) {
                    int col = n0 + wn * 32 + ni * 8 + 2 * tig;
                    int p = col >> 4, t = col & 15;
                    __nv_bfloat162 v = __floats2bfloat162_rn(acc[mi][ni][2 * half],
                                                             acc[mi][ni][2 * half + 1]);
                    *(__nv_bfloat162*)(dst + (base + p) * DT + d * 16 + t) = v;
                }
            }
    }
}

// ---------------------------------------------------------------------------
// energy[bh][p][permq(q)] = sum_dt K[p][dt] Q[q][dt]   (bf16 mma, 2-stage)
// ---------------------------------------------------------------------------
__global__ __launch_bounds__(256, 3) void energy_kernel() {
    extern __shared__ unsigned smu[];
    const int TSZ = 128 * SEW;     // 2560 words
    const int STG = 2 * TSZ;       // per-stage words (A+B)
    int tid = threadIdx.x, lane = tid & 31, warp = tid >> 5;
    int g = lane >> 2, tig = lane & 3, wm = warp >> 2, wn = warp & 3;
    int bh = blockIdx.z, m0 = blockIdx.y * 128, n0 = blockIdx.x * 128;
    const __nv_bfloat16* Ap = g_K + (size_t)bh * P_ * DT + (size_t)m0 * DT;
    const __nv_bfloat16* Bp = g_Q + (size_t)bh * P_ * DT + (size_t)n0 * DT;

    float acc[4][4][4]; ZERO_ACC(acc);
    const int NIT = DT / 32;   // 16
    load_ebf(smu, Ap, tid);          load_ebf(smu + TSZ, Bp, tid);          cpc();
    load_ebf(smu + STG, Ap + 32, tid); load_ebf(smu + STG + TSZ, Bp + 32, tid); cpc();
    for (int i = 0; i < NIT; i++) {
        cpw1(); __syncthreads();
        const unsigned* As = smu + (i & 1) * STG;
        comp_ebf(As, As + TSZ, acc, wm, wn, g, tig);
        __syncthreads();
        if (i + 2 < NIT) {
            load_ebf(smu + (i & 1) * STG, Ap + (i + 2) * 32, tid);
            load_ebf(smu + (i & 1) * STG + TSZ, Bp + (i + 2) * 32, tid);
        }
        cpc();
    }

    float* Ep = g_E + (size_t)bh * P_ * P_;
#pragma unroll
    for (int mi = 0; mi < 4; mi++) {
        int p = m0 + wm * 64 + mi * 16 + g;
#pragma unroll
        for (int ni = 0; ni < 4; ni++)
#pragma unroll
            for (int e = 0; e < 4; e++) {
                int q = n0 + wn * 32 + ni * 8 + 2 * tig + (e & 1);
                int qp = (q & ~15) | ((q & 7) << 1) | ((q >> 3) & 1);
                Ep[(size_t)(p + ((e >= 2) ? 8 : 0)) * P_ + qp] = acc[mi][ni][e];
            }
    }
}

// ---------------------------------------------------------------------------
// softmax rows of E / sqrt(512), in place; rounds output to tf32
// ---------------------------------------------------------------------------
__global__ __launch_bounds__(256) void softmax_kernel() {
    int p = blockIdx.x, bh = blockIdx.y;
    float* row = g_E + ((size_t)bh * P_ + p) * P_;
    int tid = threadIdx.x, lane = tid & 31, warp = tid >> 5;
    const float invs = 0.044194173824159216f;

    float4 v = *(const float4*)(row + tid * 4);
    float lx = v.x * invs, ly = v.y * invs, lz = v.z * invs, lw = v.w * invs;

    __shared__ float smx[8];
    float m = fmaxf(fmaxf(lx, ly), fmaxf(lz, lw));
#pragma unroll
    for (int off = 16; off > 0; off >>= 1) m = fmaxf(m, __shfl_xor_sync(0xffffffffu, m, off));
    if (lane == 0) smx[warp] = m;
    __syncthreads();
    m = smx[0];
#pragma unroll
    for (int i = 1; i < 8; i++) m = fmaxf(m, smx[i]);
    __syncthreads();

    float ex = __expf(lx - m), ey = __expf(ly - m), ez = __expf(lz - m), ew = __expf(lw - m);
    float s = ex + ey + ez + ew;
#pragma unroll
    for (int off = 16; off > 0; off >>= 1) s += __shfl_xor_sync(0xffffffffu, s, off);
    if (lane == 0) smx[warp] = s;
    __syncthreads();
    s = smx[0];
#pragma unroll
    for (int i = 1; i < 8; i++) s += smx[i];
    float inv = 1.0f / s;
    *(float4*)(row + tid * 4) =
        make_float4(rtf(ex * inv), rtf(ey * inv), rtf(ez * inv), rtf(ew * inv));
}

// ---------------------------------------------------------------------------
// av: out[q][dt] = sum_p attn[p][q] V[p][dt]   (tf32, 2-stage, 3 CTAs/SM)
// ---------------------------------------------------------------------------
__global__ __launch_bounds__(256, 3) void av_kernel(float* __restrict__ out) {
    extern __shared__ float sm[];
    const int STG = 8704;
    int tid = threadIdx.x, lane = tid & 31, warp = tid >> 5;
    int g = lane >> 2, tig = lane & 3, wm = warp >> 2, wn = warp & 3;
    int bh = blockIdx.z, b = bh >> 3, h = bh & 7;
    int m0 = blockIdx.y * 128;   // q
    int n0 = blockIdx.x * 128;   // dt
    const float* Ap = g_E + (size_t)bh * P_ * P_ + m0;
    const float* Bp = g_V + (size_t)bh * P_ * DT + n0;

    float acc[4][4][4]; ZERO_ACC(acc);
    const int NIT = P_ / 32;   // 32
    load_t(sm, Ap, P_, tid);                 load_t(sm + 4352, Bp, DT, tid);                 cpc();
    load_t(sm + STG, Ap + 32 * P_, P_, tid); load_t(sm + STG + 4352, Bp + 32 * DT, DT, tid); cpc();
    for (int i = 0; i < NIT; i++) {
        cpw1(); __syncthreads();
        const float* S = sm + (i & 1) * STG;
        comp_av(S, S + 4352, acc, wm, wn, g, tig);
        __syncthreads();
        if (i + 2 < NIT) {
            load_t(sm + (i & 1) * STG, Ap + (size_t)(i + 2) * 32 * P_, P_, tid);
            load_t(sm + (i & 1) * STG + 4352, Bp + (size_t)(i + 2) * 32 * DT, DT, tid);
        }
        cpc();
    }

#pragma unroll
    for (int mi = 0; mi < 4; mi++)
#pragma unroll
        for (int half = 0; half < 2; half++) {
            int q = m0 + wm * 64 + mi * 16 + g + half * 8;
#pragma unroll
            for (int ni = 0; ni < 4; ni++) {
                int n = n0 + wn * 32 + ni * 8 + 2 * tig;
                int d = n >> 4, t = n & 15;
                float2 v = make_float2(acc[mi][ni][2 * half], acc[mi][ni][2 * half + 1]);
                *(float2*)(out + (((size_t)b * C_ + h * 32 + d) * P_ + q) * T_ + t) = v;
            }
        }
}

// ---------------------------------------------------------------------------
extern "C" void kernel_launch(void* const* d_in, const int* in_sizes, int n_in,
                              void* d_out, int out_size) {
    const float* x  = (const float*)d_in[0];
    const float* Wk = (const float*)d_in[1];
    const float* Wq = (const float*)d_in[2];
    const float* Wv = (const float*)d_in[3];
    float* out = (float*)d_out;

    const int SM_PROJ = 3 * (4608 + 4352) * 4;       // 107520
    const int SM_EN   = 2 * 2 * 128 * SEW * 4;       // 40960
    const int SM_AV   = 2 * 8704 * 4;                // 69632
    cudaFuncSetAttribute(proj_kernel,   cudaFuncAttributeMaxDynamicSharedMemorySize, SM_PROJ);
    cudaFuncSetAttribute(energy_kernel, cudaFuncAttributeMaxDynamicSharedMemorySize, SM_EN);
    cudaFuncSetAttribute(av_kernel,     cudaFuncAttributeMaxDynamicSharedMemorySize, SM_AV);

    proj_kernel<<<dim3(PT / 128, C_ / 128, 3 * B_), 256, SM_PROJ>>>(x, Wk, Wq, Wv);
    energy_kernel<<<dim3(P_ / 128, P_ / 128, BH), 256, SM_EN>>>();
    softmax_kernel<<<dim3(P_, BH), 256>>>();
    av_kernel<<<dim3(DT / 128, P_ / 128, BH), 256, SM_AV>>>(out);
}

// round 6
// speedup vs baseline: 1.2625x; 1.2625x over previous
#include <cuda_runtime.h>
#include <cuda_bf16.h>

#define B_  8
#define C_  256
#define P_  1024
#define T_  16
#define DT  512      // D*T
#define PT  16384    // P*T
#define BH  64

// Scratch
__device__ __nv_bfloat16 g_K[(size_t)BH * P_ * DT];  // [bh][p][dt] bf16
__device__ __nv_bfloat16 g_Q[(size_t)BH * P_ * DT];  // [bh][p][dt] bf16
__device__ float g_V[(size_t)BH * P_ * DT];          // [bh][p][perm32(dt)] tf32-rounded
__device__ float g_E[(size_t)BH * P_ * P_];          // [bh][p][permq16(q)]

#define SA 36     // proj row-k stride (words)
#define ST 136    // k-major stride (words)
#define SEW 20    // energy bf16 row stride (32-bit words)
#define NTHR 256

__device__ __forceinline__ unsigned f2tf(float f) {
    unsigned u; asm("cvt.rna.tf32.f32 %0, %1;" : "=r"(u) : "f"(f)); return u;
}
__device__ __forceinline__ float rtf(float f) { return __uint_as_float(f2tf(f)); }

__device__ __forceinline__ void mma8(float* c, unsigned a0, unsigned a1, unsigned a2, unsigned a3,
                                     unsigned b0, unsigned b1) {
    asm volatile(
        "mma.sync.aligned.m16n8k8.row.col.f32.tf32.tf32.f32 "
        "{%0,%1,%2,%3},{%4,%5,%6,%7},{%8,%9},{%0,%1,%2,%3};"
        : "+f"(c[0]), "+f"(c[1]), "+f"(c[2]), "+f"(c[3])
        : "r"(a0), "r"(a1), "r"(a2), "r"(a3), "r"(b0), "r"(b1));
}
__device__ __forceinline__ void mmabf(float* c, unsigned a0, unsigned a1, unsigned a2, unsigned a3,
                                      unsigned b0, unsigned b1) {
    asm volatile(
        "mma.sync.aligned.m16n8k16.row.col.f32.bf16.bf16.f32 "
        "{%0,%1,%2,%3},{%4,%5,%6,%7},{%8,%9},{%0,%1,%2,%3};"
        : "+f"(c[0]), "+f"(c[1]), "+f"(c[2]), "+f"(c[3])
        : "r"(a0), "r"(a1), "r"(a2), "r"(a3), "r"(b0), "r"(b1));
}
__device__ __forceinline__ void cp16(void* s, const void* g) {
    unsigned a = (unsigned)__cvta_generic_to_shared(s);
    asm volatile("cp.async.cg.shared.global [%0], [%1], 16;" :: "r"(a), "l"(g));
}
__device__ __forceinline__ void cpc()  { asm volatile("cp.async.commit_group;"); }
__device__ __forceinline__ void cpw1() { asm volatile("cp.async.wait_group 1;"); }

// ---- tile loaders ----
__device__ __forceinline__ void load_rk(float* buf, const float* g, int ldg, int tid) {
#pragma unroll
    for (int j = 0; j < 4; j++) {
        int c = tid + j * NTHR;
        int row = c >> 3, col = (c & 7) * 4;
        cp16(buf + row * SA + col, g + (size_t)row * ldg + col);
    }
}
__device__ __forceinline__ void load_t(float* buf, const float* g, int ldg, int tid) {
#pragma unroll
    for (int j = 0; j < 4; j++) {
        int c = tid + j * NTHR;
        int row = c >> 5, col = (c & 31) * 4;
        cp16(buf + row * ST + col, g + (size_t)row * ldg + col);
    }
}
// energy: 128 rows x 32 bf16 (64B/row = 4 x 16B), stride SEW words
__device__ __forceinline__ void load_ebf(unsigned* buf, const __nv_bfloat16* g, int tid) {
#pragma unroll
    for (int j = 0; j < 2; j++) {
        int c = tid + j * NTHR;
        int row = c >> 2, ch = c & 3;
        cp16(buf + row * SEW + ch * 4, g + (size_t)row * DT + ch * 8);
    }
}

// ---- proj compute: A row-k (cvt), B k-major (cvt), tf32 ----
__device__ __forceinline__ void comp_rk_t(const float* As, const float* Bt, float acc[4][4][4],
                                          int wm, int wn, int g, int tig) {
#pragma unroll
    for (int kk = 0; kk < 4; kk++) {
        int k0 = kk * 8 + tig;
        unsigned a[4][4];
#pragma unroll
        for (int mi = 0; mi < 4; mi++) {
            int r = wm * 64 + mi * 16 + g;
            a[mi][0] = f2tf(As[r * SA + k0]);       a[mi][1] = f2tf(As[(r + 8) * SA + k0]);
            a[mi][2] = f2tf(As[r * SA + k0 + 4]);   a[mi][3] = f2tf(As[(r + 8) * SA + k0 + 4]);
        }
#pragma unroll
        for (int ni = 0; ni < 4; ni++) {
            int n = wn * 32 + ni * 8 + g;
            unsigned b0 = f2tf(Bt[k0 * ST + n]), b1 = f2tf(Bt[(k0 + 4) * ST + n]);
#pragma unroll
            for (int mi = 0; mi < 4; mi++)
                mma8(acc[mi][ni], a[mi][0], a[mi][1], a[mi][2], a[mi][3], b0, b1);
        }
    }
}

// ---- energy compute: bf16 k16, both operands row-k, stride SEW ----
__device__ __forceinline__ void comp_ebf(const unsigned* As, const unsigned* Bs, float acc[4][4][4],
                                         int wm, int wn, int g, int tig) {
#pragma unroll
    for (int c = 0; c < 2; c++) {
        int w0 = c * 8 + tig;
        unsigned b[4][2];
#pragma unroll
        for (int ni = 0; ni < 4; ni++) {
            int rn = wn * 32 + ni * 8 + g;
            b[ni][0] = Bs[rn * SEW + w0]; b[ni][1] = Bs[rn * SEW + w0 + 4];
        }
#pragma unroll
        for (int mi = 0; mi < 4; mi++) {
            int r = wm * 64 + mi * 16 + g;
            unsigned a0 = As[r * SEW + w0],     a1 = As[(r + 8) * SEW + w0];
            unsigned a2 = As[r * SEW + w0 + 4], a3 = As[(r + 8) * SEW + w0 + 4];
#pragma unroll
            for (int ni = 0; ni < 4; ni++)
                mmabf(acc[mi][ni], a0, a1, a2, a3, b[ni][0], b[ni][1]);
        }
    }
}

// ---- av compute: A k-major (q pair-perm, LDS.64), B k-major (col-perm, LDS.128), tf32 ----
__device__ __forceinline__ void comp_av(const float* At, const float* Bt, float acc[4][4][4],
                                        int wm, int wn, int g, int tig) {
#pragma unroll
    for (int kk = 0; kk < 4; kk++) {
        int k0 = kk * 8 + tig;
        float4 vb0 = *(const float4*)(Bt + k0 * ST + wn * 32 + 4 * g);
        float4 vb1 = *(const float4*)(Bt + (k0 + 4) * ST + wn * 32 + 4 * g);
        const float* b0p = &vb0.x;
        const float* b1p = &vb1.x;
#pragma unroll
        for (int mi = 0; mi < 4; mi++) {
            int cb = wm * 64 + mi * 16 + 2 * g;
            float2 lo = *(const float2*)(At + k0 * ST + cb);
            float2 hi = *(const float2*)(At + (k0 + 4) * ST + cb);
            unsigned a0 = __float_as_uint(lo.x), a1 = __float_as_uint(lo.y);
            unsigned a2 = __float_as_uint(hi.x), a3 = __float_as_uint(hi.y);
#pragma unroll
            for (int ni = 0; ni < 4; ni++)
                mma8(acc[mi][ni], a0, a1, a2, a3,
                     __float_as_uint(b0p[ni]), __float_as_uint(b1p[ni]));
        }
    }
}

#define ZERO_ACC(acc) \
    _Pragma("unroll") for (int mi = 0; mi < 4; mi++) \
    _Pragma("unroll") for (int ni = 0; ni < 4; ni++) \
    _Pragma("unroll") for (int e = 0; e < 4; e++) acc[mi][ni][e] = 0.f;

// ---------------------------------------------------------------------------
// proj: Y[o, pt] = sum_c W[o,c] x[b,c,pt]
// K,Q -> bf16 [p][dt]; V -> fp32 tf32-rounded [p][perm32(dt)]
// ---------------------------------------------------------------------------
__global__ __launch_bounds__(256) void proj_kernel(const float* __restrict__ x,
                                                   const float* __restrict__ Wk,
                                                   const float* __restrict__ Wq,
                                                   const float* __restrict__ Wv) {
    extern __shared__ float sm[];
    const int STG = 4608 + 4352;
    int tid = threadIdx.x, lane = tid & 31, warp = tid >> 5;
    int g = lane >> 2, tig = lane & 3, wm = warp >> 2, wn = warp & 3;
    int bz = blockIdx.z, w = bz % 3, b = bz / 3;
    const float* W = (w == 0) ? Wk : (w == 1) ? Wq : Wv;
    int m0 = blockIdx.y * 128, n0 = blockIdx.x * 128;
    const float* Ap = W + (size_t)m0 * C_;
    const float* Bp = x + (size_t)b * C_ * PT + n0;

    float acc[4][4][4]; ZERO_ACC(acc);
    const int NIT = C_ / 32;
    load_rk(sm, Ap, C_, tid);            load_t(sm + 4608, Bp, PT, tid);            cpc();
    load_rk(sm + STG, Ap + 32, C_, tid); load_t(sm + STG + 4608, Bp + 32 * PT, PT, tid); cpc();
    int sc = 0, sl = 2;
    for (int i = 0; i < NIT; i++) {
        cpw1(); __syncthreads();
        if (i + 2 < NIT) {
            load_rk(sm + sl * STG, Ap + (i + 2) * 32, C_, tid);
            load_t(sm + sl * STG + 4608, Bp + (size_t)(i + 2) * 32 * PT, PT, tid);
        }
        cpc();
        comp_rk_t(sm + sc * STG, sm + sc * STG + 4608, acc, wm, wn, g, tig);
        sc = (sc == 2) ? 0 : sc + 1; sl = (sl == 2) ? 0 : sl + 1;
    }

    if (w == 2) {
        // V: fp32, column-permuted within dt-32 groups
#pragma unroll
        for (int mi = 0; mi < 4; mi++)
#pragma unroll
            for (int half = 0; half < 2; half++) {
                int o = m0 + wm * 64 + mi * 16 + g + half * 8;
                int h = o >> 5, d = o & 31;
                size_t base = ((size_t)(b * 8 + h)) * P_;
#pragma unroll
                for (int ni = 0; ni < 4; ni++)
#pragma unroll
                    for (int e = 0; e < 2; e++) {
                        int col = n0 + wn * 32 + ni * 8 + 2 * tig + e;
                        int p = col >> 4, t = col & 15;
                        int dt = d * 16 + t;
                        int dtp = (dt & ~31) | (4 * (dt & 7) + ((dt >> 3) & 3));
                        g_V[(base + p) * DT + dtp] = rtf(acc[mi][ni][2 * half + e]);
                    }
            }
    } else {
        __nv_bfloat16* dst = (w == 0) ? g_K : g_Q;
#pragma unroll
        for (int mi = 0; mi < 4; mi++)
#pragma unroll
            for (int half = 0; half < 2; half++) {
                int o = m0 + wm * 64 + mi * 16 + g + half * 8;
                int h = o >> 5, d = o & 31;
                size_t base = ((size_t)(b * 8 + h)) * P_;
#pragma unroll
                for (int ni = 0; ni < 4; ni++) {
                    int col = n0 + wn * 32 + ni * 8 + 2 * tig;
                    int p = col >> 4, t = col & 15;
                    __nv_bfloat162 v = __floats2bfloat162_rn(acc[mi][ni][2 * half],
                                                             acc[mi][ni][2 * half + 1]);
                    *(__nv_bfloat162*)(dst + (base + p) * DT + d * 16 + t) = v;
                }
            }
    }
}

// ---------------------------------------------------------------------------
// energy[bh][p][permq(q)] = sum_dt K[p][dt] Q[q][dt]   (bf16 mma, 3-stage)
// ---------------------------------------------------------------------------
__global__ __launch_bounds__(256) void energy_kernel() {
    extern __shared__ unsigned smu[];
    const int TSZ = 128 * SEW;     // 2560 words
    const int STG = 2 * TSZ;       // per-stage words (A+B)
    int tid = threadIdx.x, lane = tid & 31, warp = tid >> 5;
    int g = lane >> 2, tig = lane & 3, wm = warp >> 2, wn = warp & 3;
    int bh = blockIdx.z, m0 = blockIdx.y * 128, n0 = blockIdx.x * 128;
    const __nv_bfloat16* Ap = g_K + (size_t)bh * P_ * DT + (size_t)m0 * DT;
    const __nv_bfloat16* Bp = g_Q + (size_t)bh * P_ * DT + (size_t)n0 * DT;

    float acc[4][4][4]; ZERO_ACC(acc);
    const int NIT = DT / 32;   // 16
    load_ebf(smu, Ap, tid);            load_ebf(smu + TSZ, Bp, tid);            cpc();
    load_ebf(smu + STG, Ap + 32, tid); load_ebf(smu + STG + TSZ, Bp + 32, tid); cpc();
    int sc = 0, sl = 2;
    for (int i = 0; i < NIT; i++) {
        cpw1(); __syncthreads();
        if (i + 2 < NIT) {
            load_ebf(smu + sl * STG, Ap + (i + 2) * 32, tid);
            load_ebf(smu + sl * STG + TSZ, Bp + (i + 2) * 32, tid);
        }
        cpc();
        comp_ebf(smu + sc * STG, smu + sc * STG + TSZ, acc, wm, wn, g, tig);
        sc = (sc == 2) ? 0 : sc + 1; sl = (sl == 2) ? 0 : sl + 1;
    }

    float* Ep = g_E + (size_t)bh * P_ * P_;
#pragma unroll
    for (int mi = 0; mi < 4; mi++) {
        int p = m0 + wm * 64 + mi * 16 + g;
#pragma unroll
        for (int ni = 0; ni < 4; ni++)
#pragma unroll
            for (int e = 0; e < 4; e++) {
                int q = n0 + wn * 32 + ni * 8 + 2 * tig + (e & 1);
                int qp = (q & ~15) | ((q & 7) << 1) | ((q >> 3) & 1);
                Ep[(size_t)(p + ((e >= 2) ? 8 : 0)) * P_ + qp] = acc[mi][ni][e];
            }
    }
}

// ---------------------------------------------------------------------------
// softmax rows of E / sqrt(512), in place; rounds output to tf32
// ---------------------------------------------------------------------------
__global__ __launch_bounds__(256) void softmax_kernel() {
    int p = blockIdx.x, bh = blockIdx.y;
    float* row = g_E + ((size_t)bh * P_ + p) * P_;
    int tid = threadIdx.x, lane = tid & 31, warp = tid >> 5;
    const float invs = 0.044194173824159216f;

    float4 v = *(const float4*)(row + tid * 4);
    float lx = v.x * invs, ly = v.y * invs, lz = v.z * invs, lw = v.w * invs;

    __shared__ float smx[8];
    float m = fmaxf(fmaxf(lx, ly), fmaxf(lz, lw));
#pragma unroll
    for (int off = 16; off > 0; off >>= 1) m = fmaxf(m, __shfl_xor_sync(0xffffffffu, m, off));
    if (lane == 0) smx[warp] = m;
    __syncthreads();
    m = smx[0];
#pragma unroll
    for (int i = 1; i < 8; i++) m = fmaxf(m, smx[i]);
    __syncthreads();

    float ex = __expf(lx - m), ey = __expf(ly - m), ez = __expf(lz - m), ew = __expf(lw - m);
    float s = ex + ey + ez + ew;
#pragma unroll
    for (int off = 16; off > 0; off >>= 1) s += __shfl_xor_sync(0xffffffffu, s, off);
    if (lane == 0) smx[warp] = s;
    __syncthreads();
    s = smx[0];
#pragma unroll
    for (int i = 1; i < 8; i++) s += smx[i];
    float inv = 1.0f / s;
    *(float4*)(row + tid * 4) =
        make_float4(rtf(ex * inv), rtf(ey * inv), rtf(ez * inv), rtf(ew * inv));
}

// ---------------------------------------------------------------------------
// av: out[q][dt] = sum_p attn[p][q] V[p][dt]   (tf32, 3-stage, natural regs)
// ---------------------------------------------------------------------------
__global__ __launch_bounds__(256) void av_kernel(float* __restrict__ out) {
    extern __shared__ float sm[];
    const int STG = 8704;
    int tid = threadIdx.x, lane = tid & 31, warp = tid >> 5;
    int g = lane >> 2, tig = lane & 3, wm = warp >> 2, wn = warp & 3;
    int bh = blockIdx.z, b = bh >> 3, h = bh & 7;
    int m0 = blockIdx.y * 128;   // q
    int n0 = blockIdx.x * 128;   // dt
    const float* Ap = g_E + (size_t)bh * P_ * P_ + m0;
    const float* Bp = g_V + (size_t)bh * P_ * DT + n0;

    float acc[4][4][4]; ZERO_ACC(acc);
    const int NIT = P_ / 32;   // 32
    load_t(sm, Ap, P_, tid);                 load_t(sm + 4352, Bp, DT, tid);                 cpc();
    load_t(sm + STG, Ap + 32 * P_, P_, tid); load_t(sm + STG + 4352, Bp + 32 * DT, DT, tid); cpc();
    int sc = 0, sl = 2;
    for (int i = 0; i < NIT; i++) {
        cpw1(); __syncthreads();
        if (i + 2 < NIT) {
            load_t(sm + sl * STG, Ap + (size_t)(i + 2) * 32 * P_, P_, tid);
            load_t(sm + sl * STG + 4352, Bp + (size_t)(i + 2) * 32 * DT, DT, tid);
        }
        cpc();
        comp_av(sm + sc * STG, sm + sc * STG + 4352, acc, wm, wn, g, tig);
        sc = (sc == 2) ? 0 : sc + 1; sl = (sl == 2) ? 0 : sl + 1;
    }

#pragma unroll
    for (int mi = 0; mi < 4; mi++)
#pragma unroll
        for (int half = 0; half < 2; half++) {
            int q = m0 + wm * 64 + mi * 16 + g + half * 8;
#pragma unroll
            for (int ni = 0; ni < 4; ni++) {
                int n = n0 + wn * 32 + ni * 8 + 2 * tig;
                int d = n >> 4, t = n & 15;
                float2 v = make_float2(acc[mi][ni][2 * half], acc[mi][ni][2 * half + 1]);
                *(float2*)(out + (((size_t)b * C_ + h * 32 + d) * P_ + q) * T_ + t) = v;
            }
        }
}

// ---------------------------------------------------------------------------
extern "C" void kernel_launch(void* const* d_in, const int* in_sizes, int n_in,
                              void* d_out, int out_size) {
    const float* x  = (const float*)d_in[0];
    const float* Wk = (const float*)d_in[1];
    const float* Wq = (const float*)d_in[2];
    const float* Wv = (const float*)d_in[3];
    float* out = (float*)d_out;

    const int SM_PROJ = 3 * (4608 + 4352) * 4;       // 107520
    const int SM_EN   = 3 * 2 * 128 * SEW * 4;       // 61440
    const int SM_AV   = 3 * 8704 * 4;                // 104448
    cudaFuncSetAttribute(proj_kernel,   cudaFuncAttributeMaxDynamicSharedMemorySize, SM_PROJ);
    cudaFuncSetAttribute(energy_kernel, cudaFuncAttributeMaxDynamicSharedMemorySize, SM_EN);
    cudaFuncSetAttribute(av_kernel,     cudaFuncAttributeMaxDynamicSharedMemorySize, SM_AV);

    proj_kernel<<<dim3(PT / 128, C_ / 128, 3 * B_), 256, SM_PROJ>>>(x, Wk, Wq, Wv);
    energy_kernel<<<dim3(P_ / 128, P_ / 128, BH), 256, SM_EN>>>();
    softmax_kernel<<<dim3(P_, BH), 256>>>();
    av_kernel<<<dim3(DT / 128, P_ / 128, BH), 256, SM_AV>>>(out);
}

// round 7
// speedup vs baseline: 1.4554x; 1.1528x over previous
#include <cuda_runtime.h>
#include <cuda_bf16.h>
#include <cuda_fp16.h>

#define B_  8
#define C_  256
#define P_  1024
#define T_  16
#define DT  512      // D*T
#define PT  16384    // P*T
#define BH  64

// Scratch
__device__ __nv_bfloat16 g_K[(size_t)BH * P_ * DT];  // [bh][p][dt] bf16
__device__ __nv_bfloat16 g_Q[(size_t)BH * P_ * DT];  // [bh][p][dt] bf16
__device__ __half g_Vh[(size_t)BH * P_ * DT];        // [bh][p/2][dt][2] fp16 (p-pair interleaved)
__device__ __half g_E[(size_t)BH * P_ * P_];         // [bh][p][q] fp16 raw energy
__device__ __half g_A[(size_t)BH * P_ * P_];         // [bh][q][p] fp16 attn (transposed)
__device__ float  g_S[(size_t)BH * P_];              // 1/rowsum

#define SA 36     // proj row-k stride (words)
#define ST 136    // proj k-major stride (words)
#define SEW 20    // fp16/bf16 row-k stride: 128 rows x 32 elems (words)
#define SBV 136   // av B tile word stride: 16 kpair rows x 128 dt-words
#define NTHR 256
#define INVS 0.044194173824159216f   // 1/sqrt(512)

__device__ __forceinline__ unsigned f2tf(float f) {
    unsigned u; asm("cvt.rna.tf32.f32 %0, %1;" : "=r"(u) : "f"(f)); return u;
}

__device__ __forceinline__ void mma8(float* c, unsigned a0, unsigned a1, unsigned a2, unsigned a3,
                                     unsigned b0, unsigned b1) {
    asm volatile(
        "mma.sync.aligned.m16n8k8.row.col.f32.tf32.tf32.f32 "
        "{%0,%1,%2,%3},{%4,%5,%6,%7},{%8,%9},{%0,%1,%2,%3};"
        : "+f"(c[0]), "+f"(c[1]), "+f"(c[2]), "+f"(c[3])
        : "r"(a0), "r"(a1), "r"(a2), "r"(a3), "r"(b0), "r"(b1));
}
__device__ __forceinline__ void mmabf(float* c, unsigned a0, unsigned a1, unsigned a2, unsigned a3,
                                      unsigned b0, unsigned b1) {
    asm volatile(
        "mma.sync.aligned.m16n8k16.row.col.f32.bf16.bf16.f32 "
        "{%0,%1,%2,%3},{%4,%5,%6,%7},{%8,%9},{%0,%1,%2,%3};"
        : "+f"(c[0]), "+f"(c[1]), "+f"(c[2]), "+f"(c[3])
        : "r"(a0), "r"(a1), "r"(a2), "r"(a3), "r"(b0), "r"(b1));
}
__device__ __forceinline__ void mmah(float* c, unsigned a0, unsigned a1, unsigned a2, unsigned a3,
                                     unsigned b0, unsigned b1) {
    asm volatile(
        "mma.sync.aligned.m16n8k16.row.col.f32.f16.f16.f32 "
        "{%0,%1,%2,%3},{%4,%5,%6,%7},{%8,%9},{%0,%1,%2,%3};"
        : "+f"(c[0]), "+f"(c[1]), "+f"(c[2]), "+f"(c[3])
        : "r"(a0), "r"(a1), "r"(a2), "r"(a3), "r"(b0), "r"(b1));
}
__device__ __forceinline__ void cp16(void* s, const void* g) {
    unsigned a = (unsigned)__cvta_generic_to_shared(s);
    asm volatile("cp.async.cg.shared.global [%0], [%1], 16;" :: "r"(a), "l"(g));
}
__device__ __forceinline__ void cpc()  { asm volatile("cp.async.commit_group;"); }
__device__ __forceinline__ void cpw1() { asm volatile("cp.async.wait_group 1;"); }

// ---- tile loaders ----
__device__ __forceinline__ void load_rk(float* buf, const float* g, int ldg, int tid) {
#pragma unroll
    for (int j = 0; j < 4; j++) {
        int c = tid + j * NTHR;
        int row = c >> 3, col = (c & 7) * 4;
        cp16(buf + row * SA + col, g + (size_t)row * ldg + col);
    }
}
__device__ __forceinline__ void load_t(float* buf, const float* g, int ldg, int tid) {
#pragma unroll
    for (int j = 0; j < 4; j++) {
        int c = tid + j * NTHR;
        int row = c >> 5, col = (c & 31) * 4;
        cp16(buf + row * ST + col, g + (size_t)row * ldg + col);
    }
}
// 128 rows x 32 16-bit elems (64B/row), row stride ldg (in elems), smem stride SEW words
__device__ __forceinline__ void load_h(unsigned* buf, const void* gv, int ldg, int tid) {
    const __half* g = (const __half*)gv;
#pragma unroll
    for (int j = 0; j < 2; j++) {
        int c = tid + j * NTHR;
        int row = c >> 2, ch = c & 3;
        cp16(buf + row * SEW + ch * 4, g + (size_t)row * ldg + ch * 8);
    }
}
// av B: 16 kpair rows x 512B, gmem row stride DT*2 halfs
__device__ __forceinline__ void load_v(unsigned* buf, const __half* g, int tid) {
#pragma unroll
    for (int j = 0; j < 2; j++) {
        int c = tid + j * NTHR;
        int row = c >> 5, ch = c & 31;
        cp16(buf + row * SBV + ch * 4, g + (size_t)row * (DT * 2) + ch * 8);
    }
}

// ---- proj compute: A row-k (cvt), B k-major (cvt), tf32 ----
__device__ __forceinline__ void comp_rk_t(const float* As, const float* Bt, float acc[4][4][4],
                                          int wm, int wn, int g, int tig) {
#pragma unroll
    for (int kk = 0; kk < 4; kk++) {
        int k0 = kk * 8 + tig;
        unsigned a[4][4];
#pragma unroll
        for (int mi = 0; mi < 4; mi++) {
            int r = wm * 64 + mi * 16 + g;
            a[mi][0] = f2tf(As[r * SA + k0]);       a[mi][1] = f2tf(As[(r + 8) * SA + k0]);
            a[mi][2] = f2tf(As[r * SA + k0 + 4]);   a[mi][3] = f2tf(As[(r + 8) * SA + k0 + 4]);
        }
#pragma unroll
        for (int ni = 0; ni < 4; ni++) {
            int n = wn * 32 + ni * 8 + g;
            unsigned b0 = f2tf(Bt[k0 * ST + n]), b1 = f2tf(Bt[(k0 + 4) * ST + n]);
#pragma unroll
            for (int mi = 0; mi < 4; mi++)
                mma8(acc[mi][ni], a[mi][0], a[mi][1], a[mi][2], a[mi][3], b0, b1);
        }
    }
}

// ---- energy compute: bf16 k16, both operands row-k, stride SEW ----
__device__ __forceinline__ void comp_ebf(const unsigned* As, const unsigned* Bs, float acc[4][4][4],
                                         int wm, int wn, int g, int tig) {
#pragma unroll
    for (int c = 0; c < 2; c++) {
        int w0 = c * 8 + tig;
        unsigned b[4][2];
#pragma unroll
        for (int ni = 0; ni < 4; ni++) {
            int rn = wn * 32 + ni * 8 + g;
            b[ni][0] = Bs[rn * SEW + w0]; b[ni][1] = Bs[rn * SEW + w0 + 4];
        }
#pragma unroll
        for (int mi = 0; mi < 4; mi++) {
            int r = wm * 64 + mi * 16 + g;
            unsigned a0 = As[r * SEW + w0],     a1 = As[(r + 8) * SEW + w0];
            unsigned a2 = As[r * SEW + w0 + 4], a3 = As[(r + 8) * SEW + w0 + 4];
#pragma unroll
            for (int ni = 0; ni < 4; ni++)
                mmabf(acc[mi][ni], a0, a1, a2, a3, b[ni][0], b[ni][1]);
        }
    }
}

// ---- av compute: fp16 k16, A row-k (stride SEW), B kpair-major (stride SBV) ----
__device__ __forceinline__ void comp_av2(const unsigned* At, const unsigned* Bt, float acc[4][4][4],
                                         int wm, int wn, int g, int tig) {
#pragma unroll
    for (int c = 0; c < 2; c++) {
        int w0 = c * 8 + tig;
        unsigned b[4][2];
#pragma unroll
        for (int ni = 0; ni < 4; ni++) {
            int n = wn * 32 + ni * 8 + g;
            b[ni][0] = Bt[w0 * SBV + n]; b[ni][1] = Bt[(w0 + 4) * SBV + n];
        }
#pragma unroll
        for (int mi = 0; mi < 4; mi++) {
            int r = wm * 64 + mi * 16 + g;
            unsigned a0 = At[r * SEW + w0],     a1 = At[(r + 8) * SEW + w0];
            unsigned a2 = At[r * SEW + w0 + 4], a3 = At[(r + 8) * SEW + w0 + 4];
#pragma unroll
            for (int ni = 0; ni < 4; ni++)
                mmah(acc[mi][ni], a0, a1, a2, a3, b[ni][0], b[ni][1]);
        }
    }
}

#define ZERO_ACC(acc) \
    _Pragma("unroll") for (int mi = 0; mi < 4; mi++) \
    _Pragma("unroll") for (int ni = 0; ni < 4; ni++) \
    _Pragma("unroll") for (int e = 0; e < 4; e++) acc[mi][ni][e] = 0.f;

// ---------------------------------------------------------------------------
// proj: Y[o, pt] = sum_c W[o,c] x[b,c,pt]
// K,Q -> bf16 [p][dt]; V -> fp16 [p/2][dt][2]
// ---------------------------------------------------------------------------
__global__ __launch_bounds__(256) void proj_kernel(const float* __restrict__ x,
                                                   const float* __restrict__ Wk,
                                                   const float* __restrict__ Wq,
                                                   const float* __restrict__ Wv) {
    extern __shared__ float sm[];
    const int STG = 4608 + 4352;
    int tid = threadIdx.x, lane = tid & 31, warp = tid >> 5;
    int g = lane >> 2, tig = lane & 3, wm = warp >> 2, wn = warp & 3;
    int bz = blockIdx.z, w = bz % 3, b = bz / 3;
    const float* W = (w == 0) ? Wk : (w == 1) ? Wq : Wv;
    int m0 = blockIdx.y * 128, n0 = blockIdx.x * 128;
    const float* Ap = W + (size_t)m0 * C_;
    const float* Bp = x + (size_t)b * C_ * PT + n0;

    float acc[4][4][4]; ZERO_ACC(acc);
    const int NIT = C_ / 32;
    load_rk(sm, Ap, C_, tid);            load_t(sm + 4608, Bp, PT, tid);            cpc();
    load_rk(sm + STG, Ap + 32, C_, tid); load_t(sm + STG + 4608, Bp + 32 * PT, PT, tid); cpc();
    int sc = 0, sl = 2;
    for (int i = 0; i < NIT; i++) {
        cpw1(); __syncthreads();
        if (i + 2 < NIT) {
            load_rk(sm + sl * STG, Ap + (i + 2) * 32, C_, tid);
            load_t(sm + sl * STG + 4608, Bp + (size_t)(i + 2) * 32 * PT, PT, tid);
        }
        cpc();
        comp_rk_t(sm + sc * STG, sm + sc * STG + 4608, acc, wm, wn, g, tig);
        sc = (sc == 2) ? 0 : sc + 1; sl = (sl == 2) ? 0 : sl + 1;
    }

    if (w == 2) {
        // V: fp16, [bh][p/2][dt][2]
#pragma unroll
        for (int mi = 0; mi < 4; mi++)
#pragma unroll
            for (int half_ = 0; half_ < 2; half_++) {
                int o = m0 + wm * 64 + mi * 16 + g + half_ * 8;
                int h = o >> 5, d = o & 31;
                size_t base = ((size_t)(b * 8 + h)) * (P_ / 2);
#pragma unroll
                for (int ni = 0; ni < 4; ni++)
#pragma unroll
                    for (int e = 0; e < 2; e++) {
                        int col = n0 + wn * 32 + ni * 8 + 2 * tig + e;
                        int p = col >> 4, t = col & 15;
                        size_t idx = (base + (p >> 1)) * (size_t)(DT * 2) + (d * 16 + t) * 2 + (p & 1);
                        g_Vh[idx] = __float2half(acc[mi][ni][2 * half_ + e]);
                    }
            }
    } else {
        __nv_bfloat16* dst = (w == 0) ? g_K : g_Q;
#pragma unroll
        for (int mi = 0; mi < 4; mi++)
#pragma unroll
            for (int half_ = 0; half_ < 2; half_++) {
                int o = m0 + wm * 64 + mi * 16 + g + half_ * 8;
                int h = o >> 5, d = o & 31;
                size_t base = ((size_t)(b * 8 + h)) * P_;
#pragma unroll
                for (int ni = 0; ni < 4; ni++) {
                    int col = n0 + wn * 32 + ni * 8 + 2 * tig;
                    int p = col >> 4, t = col & 15;
                    __nv_bfloat162 v = __floats2bfloat162_rn(acc[mi][ni][2 * half_],
                                                             acc[mi][ni][2 * half_ + 1]);
                    *(__nv_bfloat162*)(dst + (base + p) * DT + d * 16 + t) = v;
                }
            }
    }
}

// ---------------------------------------------------------------------------
// energy[bh][p][q] = sum_dt K[p][dt] Q[q][dt]   (bf16 mma, 3-stage, fp16 out)
// ---------------------------------------------------------------------------
__global__ __launch_bounds__(256) void energy_kernel() {
    extern __shared__ unsigned smu[];
    const int TSZ = 128 * SEW;     // 2560 words
    const int STG = 2 * TSZ;
    int tid = threadIdx.x, lane = tid & 31, warp = tid >> 5;
    int g = lane >> 2, tig = lane & 3, wm = warp >> 2, wn = warp & 3;
    int bh = blockIdx.z, m0 = blockIdx.y * 128, n0 = blockIdx.x * 128;
    const __nv_bfloat16* Ap = g_K + (size_t)bh * P_ * DT + (size_t)m0 * DT;
    const __nv_bfloat16* Bp = g_Q + (size_t)bh * P_ * DT + (size_t)n0 * DT;

    float acc[4][4][4]; ZERO_ACC(acc);
    const int NIT = DT / 32;   // 16
    load_h(smu, Ap, DT, tid);            load_h(smu + TSZ, Bp, DT, tid);            cpc();
    load_h(smu + STG, Ap + 32, DT, tid); load_h(smu + STG + TSZ, Bp + 32, DT, tid); cpc();
    int sc = 0, sl = 2;
    for (int i = 0; i < NIT; i++) {
        cpw1(); __syncthreads();
        if (i + 2 < NIT) {
            load_h(smu + sl * STG, Ap + (i + 2) * 32, DT, tid);
            load_h(smu + sl * STG + TSZ, Bp + (i + 2) * 32, DT, tid);
        }
        cpc();
        comp_ebf(smu + sc * STG, smu + sc * STG + TSZ, acc, wm, wn, g, tig);
        sc = (sc == 2) ? 0 : sc + 1; sl = (sl == 2) ? 0 : sl + 1;
    }

    __half* Ep = g_E + (size_t)bh * P_ * P_;
#pragma unroll
    for (int mi = 0; mi < 4; mi++) {
        int p = m0 + wm * 64 + mi * 16 + g;
#pragma unroll
        for (int ni = 0; ni < 4; ni++) {
            int q = n0 + wn * 32 + ni * 8 + 2 * tig;
            *(__half2*)(Ep + (size_t)p * P_ + q)       = __floats2half2_rn(acc[mi][ni][0], acc[mi][ni][1]);
            *(__half2*)(Ep + (size_t)(p + 8) * P_ + q) = __floats2half2_rn(acc[mi][ni][2], acc[mi][ni][3]);
        }
    }
}

// ---------------------------------------------------------------------------
// stats: 1/sum_q exp(E[p][q]/sqrt(512)) per row  (logits bounded — no max pass)
// ---------------------------------------------------------------------------
__global__ __launch_bounds__(256) void stats_kernel() {
    int bh = blockIdx.y, p0 = blockIdx.x * 128;
    int t = threadIdx.x, r = t >> 1, halfq = t & 1;
    const __half* row = g_E + ((size_t)bh * P_ + p0 + r) * P_ + halfq * 512;
    float s = 0.f;
#pragma unroll 4
    for (int i = 0; i < 64; i++) {
        uint4 u = ((const uint4*)row)[i];
        const __half2* hp = (const __half2*)&u;
#pragma unroll
        for (int j = 0; j < 4; j++) {
            float2 f = __half22float2(hp[j]);
            s += __expf(f.x * INVS) + __expf(f.y * INVS);
        }
    }
    s += __shfl_xor_sync(0xffffffffu, s, 1);
    if (halfq == 0) g_S[(size_t)bh * P_ + p0 + r] = 1.0f / s;
}

// ---------------------------------------------------------------------------
// transpose-softmax: g_A[q][p] = exp(E[p][q]/sqrt(512)) / rowsum_p, fp16
// ---------------------------------------------------------------------------
__global__ __launch_bounds__(256) void trans_kernel() {
    __shared__ __half smT[128 * 136];
    int bh = blockIdx.z, p0 = blockIdx.y * 128, q0 = blockIdx.x * 128;
    int t = threadIdx.x, r = t >> 1, qh = t & 1;
    float invr = g_S[(size_t)bh * P_ + p0 + r];
    const __half* src = g_E + ((size_t)bh * P_ + p0 + r) * P_ + q0 + qh * 64;
#pragma unroll
    for (int i = 0; i < 8; i++) {
        uint4 u = ((const uint4*)src)[i];
        const __half2* hp = (const __half2*)&u;
#pragma unroll
        for (int j = 0; j < 4; j++) {
            float2 f = __half22float2(hp[j]);
            int q = qh * 64 + i * 8 + j * 2;
            smT[q * 136 + r]       = __float2half(__expf(f.x * INVS) * invr);
            smT[(q + 1) * 136 + r] = __float2half(__expf(f.y * INVS) * invr);
        }
    }
    __syncthreads();
    __half* dst = g_A + ((size_t)bh * P_ + q0 + r) * P_ + p0;
#pragma unroll
    for (int i = 0; i < 8; i++) {
        int pw = qh * 64 + i * 8;
        uint4 u = *(const uint4*)(smT + r * 136 + pw);
        *(uint4*)(dst + pw) = u;
    }
}

// ---------------------------------------------------------------------------
// av: out[q][dt] = sum_p attn[q][p] V''[p][dt]   (fp16 mma, 3-stage)
// ---------------------------------------------------------------------------
__global__ __launch_bounds__(256) void av_kernel(float* __restrict__ out) {
    extern __shared__ unsigned smu[];
    const int ATSZ = 128 * SEW;   // 2560 words
    const int BTSZ = 16 * SBV;    // 2176 words
    const int STG = ATSZ + BTSZ;  // 4736 words
    int tid = threadIdx.x, lane = tid & 31, warp = tid >> 5;
    int g = lane >> 2, tig = lane & 3, wm = warp >> 2, wn = warp & 3;
    int bh = blockIdx.z, b = bh >> 3, h = bh & 7;
    int m0 = blockIdx.y * 128;   // q
    int n0 = blockIdx.x * 128;   // dt
    const __half* Ap = g_A + ((size_t)bh * P_ + m0) * P_;          // rows q, cols p
    const __half* Bp = g_Vh + (size_t)bh * P_ * DT + (size_t)n0 * 2;  // kpair rows

    float acc[4][4][4]; ZERO_ACC(acc);
    const int NIT = P_ / 32;   // 32
    load_h(smu, Ap, P_, tid);                         load_v(smu + ATSZ, Bp, tid);                          cpc();
    load_h(smu + STG, Ap + 32, P_, tid);              load_v(smu + STG + ATSZ, Bp + 16 * (DT * 2), tid);    cpc();
    int sc = 0, sl = 2;
    for (int i = 0; i < NIT; i++) {
        cpw1(); __syncthreads();
        if (i + 2 < NIT) {
            load_h(smu + sl * STG, Ap + (i + 2) * 32, P_, tid);
            load_v(smu + sl * STG + ATSZ, Bp + (size_t)(i + 2) * 16 * (DT * 2), tid);
        }
        cpc();
        comp_av2(smu + sc * STG, smu + sc * STG + ATSZ, acc, wm, wn, g, tig);
        sc = (sc == 2) ? 0 : sc + 1; sl = (sl == 2) ? 0 : sl + 1;
    }

#pragma unroll
    for (int mi = 0; mi < 4; mi++)
#pragma unroll
        for (int half_ = 0; half_ < 2; half_++) {
            int q = m0 + wm * 64 + mi * 16 + g + half_ * 8;
#pragma unroll
            for (int ni = 0; ni < 4; ni++) {
                int n = n0 + wn * 32 + ni * 8 + 2 * tig;
                int d = n >> 4, t = n & 15;
                float2 v = make_float2(acc[mi][ni][2 * half_], acc[mi][ni][2 * half_ + 1]);
                *(float2*)(out + (((size_t)b * C_ + h * 32 + d) * P_ + q) * T_ + t) = v;
            }
        }
}

// ---------------------------------------------------------------------------
extern "C" void kernel_launch(void* const* d_in, const int* in_sizes, int n_in,
                              void* d_out, int out_size) {
    const float* x  = (const float*)d_in[0];
    const float* Wk = (const float*)d_in[1];
    const float* Wq = (const float*)d_in[2];
    const float* Wv = (const float*)d_in[3];
    float* out = (float*)d_out;

    const int SM_PROJ = 3 * (4608 + 4352) * 4;               // 107520
    const int SM_EN   = 3 * 2 * 128 * SEW * 4;               // 61440
    const int SM_AV   = 3 * (128 * SEW + 16 * SBV) * 4;      // 56832
    cudaFuncSetAttribute(proj_kernel,   cudaFuncAttributeMaxDynamicSharedMemorySize, SM_PROJ);
    cudaFuncSetAttribute(energy_kernel, cudaFuncAttributeMaxDynamicSharedMemorySize, SM_EN);
    cudaFuncSetAttribute(av_kernel,     cudaFuncAttributeMaxDynamicSharedMemorySize, SM_AV);

    proj_kernel<<<dim3(PT / 128, C_ / 128, 3 * B_), 256, SM_PROJ>>>(x, Wk, Wq, Wv);
    energy_kernel<<<dim3(P_ / 128, P_ / 128, BH), 256, SM_EN>>>();
    stats_kernel<<<dim3(P_ / 128, BH), 256>>>();
    trans_kernel<<<dim3(P_ / 128, P_ / 128, BH), 256>>>();
    av_kernel<<<dim3(DT / 128, P_ / 128, BH), 256, SM_AV>>>(out);
}

// round 9
// speedup vs baseline: 1.5112x; 1.0384x over previous
#include <cuda_runtime.h>
#include <cuda_bf16.h>
#include <cuda_fp16.h>

#define B_  8
#define C_  256
#define P_  1024
#define T_  16
#define DT  512      // D*T
#define PT  16384    // P*T
#define BH  64

// Scratch
__device__ __nv_bfloat16 g_K[(size_t)BH * P_ * DT];  // [bh][p][dt] bf16
__device__ __nv_bfloat16 g_Q[(size_t)BH * P_ * DT];  // [bh][p][dt] bf16
__device__ __half g_Vh[(size_t)BH * P_ * DT];        // [bh][p/2][dt][2] fp16 (p-pair interleaved)
__device__ __half g_E[(size_t)BH * P_ * P_];         // [bh][q][p] fp16 = exp(energy/sqrt(512))
__device__ float  g_S[(size_t)BH * P_];              // 1/colsum (softmax denominator per p)

#define SA 36     // proj row-k stride (words)
#define ST 136    // proj k-major stride (words)
#define SEW 20    // fp16/bf16 row-k stride: 128 rows x 32 elems (words)
#define SBV 136   // av B tile word stride: 16 kpair rows x 128 dt-words
#define NTHR 256
#define INVS 0.044194173824159216f   // 1/sqrt(512)

__device__ __forceinline__ unsigned f2tf(float f) {
    unsigned u; asm("cvt.rna.tf32.f32 %0, %1;" : "=r"(u) : "f"(f)); return u;
}

__device__ __forceinline__ void mma8(float* c, unsigned a0, unsigned a1, unsigned a2, unsigned a3,
                                     unsigned b0, unsigned b1) {
    asm volatile(
        "mma.sync.aligned.m16n8k8.row.col.f32.tf32.tf32.f32 "
        "{%0,%1,%2,%3},{%4,%5,%6,%7},{%8,%9},{%0,%1,%2,%3};"
        : "+f"(c[0]), "+f"(c[1]), "+f"(c[2]), "+f"(c[3])
        : "r"(a0), "r"(a1), "r"(a2), "r"(a3), "r"(b0), "r"(b1));
}
__device__ __forceinline__ void mmabf(float* c, unsigned a0, unsigned a1, unsigned a2, unsigned a3,
                                      unsigned b0, unsigned b1) {
    asm volatile(
        "mma.sync.aligned.m16n8k16.row.col.f32.bf16.bf16.f32 "
        "{%0,%1,%2,%3},{%4,%5,%6,%7},{%8,%9},{%0,%1,%2,%3};"
        : "+f"(c[0]), "+f"(c[1]), "+f"(c[2]), "+f"(c[3])
        : "r"(a0), "r"(a1), "r"(a2), "r"(a3), "r"(b0), "r"(b1));
}
__device__ __forceinline__ void mmah(float* c, unsigned a0, unsigned a1, unsigned a2, unsigned a3,
                                     unsigned b0, unsigned b1) {
    asm volatile(
        "mma.sync.aligned.m16n8k16.row.col.f32.f16.f16.f32 "
        "{%0,%1,%2,%3},{%4,%5,%6,%7},{%8,%9},{%0,%1,%2,%3};"
        : "+f"(c[0]), "+f"(c[1]), "+f"(c[2]), "+f"(c[3])
        : "r"(a0), "r"(a1), "r"(a2), "r"(a3), "r"(b0), "r"(b1));
}
__device__ __forceinline__ void cp16(void* s, const void* g) {
    unsigned a = (unsigned)__cvta_generic_to_shared(s);
    asm volatile("cp.async.cg.shared.global [%0], [%1], 16;" :: "r"(a), "l"(g));
}
__device__ __forceinline__ void cpc()  { asm volatile("cp.async.commit_group;"); }
__device__ __forceinline__ void cpw1() { asm volatile("cp.async.wait_group 1;"); }

// ---- tile loaders ----
__device__ __forceinline__ void load_rk(float* buf, const float* g, int ldg, int tid) {
#pragma unroll
    for (int j = 0; j < 4; j++) {
        int c = tid + j * NTHR;
        int row = c >> 3, col = (c & 7) * 4;
        cp16(buf + row * SA + col, g + (size_t)row * ldg + col);
    }
}
__device__ __forceinline__ void load_t(float* buf, const float* g, int ldg, int tid) {
#pragma unroll
    for (int j = 0; j < 4; j++) {
        int c = tid + j * NTHR;
        int row = c >> 5, col = (c & 31) * 4;
        cp16(buf + row * ST + col, g + (size_t)row * ldg + col);
    }
}
// 128 rows x 32 16-bit elems (64B/row), row stride ldg (in elems), smem stride SEW words
__device__ __forceinline__ void load_h(unsigned* buf, const void* gv, int ldg, int tid) {
    const __half* g = (const __half*)gv;
#pragma unroll
    for (int j = 0; j < 2; j++) {
        int c = tid + j * NTHR;
        int row = c >> 2, ch = c & 3;
        cp16(buf + row * SEW + ch * 4, g + (size_t)row * ldg + ch * 8);
    }
}
// av B: 16 kpair rows x 512B, gmem row stride DT*2 halfs
__device__ __forceinline__ void load_v(unsigned* buf, const __half* g, int tid) {
#pragma unroll
    for (int j = 0; j < 2; j++) {
        int c = tid + j * NTHR;
        int row = c >> 5, ch = c & 31;
        cp16(buf + row * SBV + ch * 4, g + (size_t)row * (DT * 2) + ch * 8);
    }
}

// ---- proj compute: A row-k (cvt), B k-major (cvt), tf32 ----
__device__ __forceinline__ void comp_rk_t(const float* As, const float* Bt, float acc[4][4][4],
                                          int wm, int wn, int g, int tig) {
#pragma unroll
    for (int kk = 0; kk < 4; kk++) {
        int k0 = kk * 8 + tig;
        unsigned a[4][4];
#pragma unroll
        for (int mi = 0; mi < 4; mi++) {
            int r = wm * 64 + mi * 16 + g;
            a[mi][0] = f2tf(As[r * SA + k0]);       a[mi][1] = f2tf(As[(r + 8) * SA + k0]);
            a[mi][2] = f2tf(As[r * SA + k0 + 4]);   a[mi][3] = f2tf(As[(r + 8) * SA + k0 + 4]);
        }
#pragma unroll
        for (int ni = 0; ni < 4; ni++) {
            int n = wn * 32 + ni * 8 + g;
            unsigned b0 = f2tf(Bt[k0 * ST + n]), b1 = f2tf(Bt[(k0 + 4) * ST + n]);
#pragma unroll
            for (int mi = 0; mi < 4; mi++)
                mma8(acc[mi][ni], a[mi][0], a[mi][1], a[mi][2], a[mi][3], b0, b1);
        }
    }
}

// ---- energy compute: bf16 k16, both operands row-k, stride SEW ----
__device__ __forceinline__ void comp_ebf(const unsigned* As, const unsigned* Bs, float acc[4][4][4],
                                         int wm, int wn, int g, int tig) {
#pragma unroll
    for (int c = 0; c < 2; c++) {
        int w0 = c * 8 + tig;
        unsigned b[4][2];
#pragma unroll
        for (int ni = 0; ni < 4; ni++) {
            int rn = wn * 32 + ni * 8 + g;
            b[ni][0] = Bs[rn * SEW + w0]; b[ni][1] = Bs[rn * SEW + w0 + 4];
        }
#pragma unroll
        for (int mi = 0; mi < 4; mi++) {
            int r = wm * 64 + mi * 16 + g;
            unsigned a0 = As[r * SEW + w0],     a1 = As[(r + 8) * SEW + w0];
            unsigned a2 = As[r * SEW + w0 + 4], a3 = As[(r + 8) * SEW + w0 + 4];
#pragma unroll
            for (int ni = 0; ni < 4; ni++)
                mmabf(acc[mi][ni], a0, a1, a2, a3, b[ni][0], b[ni][1]);
        }
    }
}

// ---- av compute: fp16 k16, A row-k (stride SEW), B kpair-major (stride SBV) ----
__device__ __forceinline__ void comp_av2(const unsigned* At, const unsigned* Bt, float acc[4][4][4],
                                         int wm, int wn, int g, int tig) {
#pragma unroll
    for (int c = 0; c < 2; c++) {
        int w0 = c * 8 + tig;
        unsigned b[4][2];
#pragma unroll
        for (int ni = 0; ni < 4; ni++) {
            int n = wn * 32 + ni * 8 + g;
            b[ni][0] = Bt[w0 * SBV + n]; b[ni][1] = Bt[(w0 + 4) * SBV + n];
        }
#pragma unroll
        for (int mi = 0; mi < 4; mi++) {
            int r = wm * 64 + mi * 16 + g;
            unsigned a0 = At[r * SEW + w0],     a1 = At[(r + 8) * SEW + w0];
            unsigned a2 = At[r * SEW + w0 + 4], a3 = At[(r + 8) * SEW + w0 + 4];
#pragma unroll
            for (int ni = 0; ni < 4; ni++)
                mmah(acc[mi][ni], a0, a1, a2, a3, b[ni][0], b[ni][1]);
        }
    }
}

#define ZERO_ACC(acc) \
    _Pragma("unroll") for (int mi = 0; mi < 4; mi++) \
    _Pragma("unroll") for (int ni = 0; ni < 4; ni++) \
    _Pragma("unroll") for (int e = 0; e < 4; e++) acc[mi][ni][e] = 0.f;

// ---------------------------------------------------------------------------
// proj: Y[o, pt] = sum_c W[o,c] x[b,c,pt]
// K,Q -> bf16 [p][dt]; V -> fp16 [p/2][dt][2]
// ---------------------------------------------------------------------------
__global__ __launch_bounds__(256) void proj_kernel(const float* __restrict__ x,
                                                   const float* __restrict__ Wk,
                                                   const float* __restrict__ Wq,
                                                   const float* __restrict__ Wv) {
    extern __shared__ float sm[];
    const int STG = 4608 + 4352;
    int tid = threadIdx.x, lane = tid & 31, warp = tid >> 5;
    int g = lane >> 2, tig = lane & 3, wm = warp >> 2, wn = warp & 3;
    int bz = blockIdx.z, w = bz % 3, b = bz / 3;
    const float* W = (w == 0) ? Wk : (w == 1) ? Wq : Wv;
    int m0 = blockIdx.y * 128, n0 = blockIdx.x * 128;
    const float* Ap = W + (size_t)m0 * C_;
    const float* Bp = x + (size_t)b * C_ * PT + n0;

    float acc[4][4][4]; ZERO_ACC(acc);
    const int NIT = C_ / 32;
    load_rk(sm, Ap, C_, tid);            load_t(sm + 4608, Bp, PT, tid);            cpc();
    load_rk(sm + STG, Ap + 32, C_, tid); load_t(sm + STG + 4608, Bp + 32 * PT, PT, tid); cpc();
    int sc = 0, sl = 2;
    for (int i = 0; i < NIT; i++) {
        cpw1(); __syncthreads();
        if (i + 2 < NIT) {
            load_rk(sm + sl * STG, Ap + (i + 2) * 32, C_, tid);
            load_t(sm + sl * STG + 4608, Bp + (size_t)(i + 2) * 32 * PT, PT, tid);
        }
        cpc();
        comp_rk_t(sm + sc * STG, sm + sc * STG + 4608, acc, wm, wn, g, tig);
        sc = (sc == 2) ? 0 : sc + 1; sl = (sl == 2) ? 0 : sl + 1;
    }

    if (w == 2) {
        // V: fp16, [bh][p/2][dt][2]
#pragma unroll
        for (int mi = 0; mi < 4; mi++)
#pragma unroll
            for (int half_ = 0; half_ < 2; half_++) {
                int o = m0 + wm * 64 + mi * 16 + g + half_ * 8;
                int h = o >> 5, d = o & 31;
                size_t base = ((size_t)(b * 8 + h)) * (P_ / 2);
#pragma unroll
                for (int ni = 0; ni < 4; ni++)
#pragma unroll
                    for (int e = 0; e < 2; e++) {
                        int col = n0 + wn * 32 + ni * 8 + 2 * tig + e;
                        int p = col >> 4, t = col & 15;
                        size_t idx = (base + (p >> 1)) * (size_t)(DT * 2) + (d * 16 + t) * 2 + (p & 1);
                        g_Vh[idx] = __float2half(acc[mi][ni][2 * half_ + e]);
                    }
            }
    } else {
        __nv_bfloat16* dst = (w == 0) ? g_K : g_Q;
#pragma unroll
        for (int mi = 0; mi < 4; mi++)
#pragma unroll
            for (int half_ = 0; half_ < 2; half_++) {
                int o = m0 + wm * 64 + mi * 16 + g + half_ * 8;
                int h = o >> 5, d = o & 31;
                size_t base = ((size_t)(b * 8 + h)) * P_;
#pragma unroll
                for (int ni = 0; ni < 4; ni++) {
                    int col = n0 + wn * 32 + ni * 8 + 2 * tig;
                    int p = col >> 4, t = col & 15;
                    __nv_bfloat162 v = __floats2bfloat162_rn(acc[mi][ni][2 * half_],
                                                             acc[mi][ni][2 * half_ + 1]);
                    *(__nv_bfloat162*)(dst + (base + p) * DT + d * 16 + t) = v;
                }
            }
    }
}

// ---------------------------------------------------------------------------
// energy (pre-transposed + exp fused):
//   g_E[bh][q][p] = exp( (sum_dt Q[q][dt] K[p][dt]) / sqrt(512) )  fp16
// A = Q (rows = q), B = K (cols = p): output lands directly in [q][p].
// ---------------------------------------------------------------------------
__global__ __launch_bounds__(256) void energy_kernel() {
    extern __shared__ unsigned smu[];
    const int TSZ = 128 * SEW;     // 2560 words
    const int STG = 2 * TSZ;
    int tid = threadIdx.x, lane = tid & 31, warp = tid >> 5;
    int g = lane >> 2, tig = lane & 3, wm = warp >> 2, wn = warp & 3;
    int bh = blockIdx.z, m0 = blockIdx.y * 128, n0 = blockIdx.x * 128;
    const __nv_bfloat16* Ap = g_Q + (size_t)bh * P_ * DT + (size_t)m0 * DT;   // q rows
    const __nv_bfloat16* Bp = g_K + (size_t)bh * P_ * DT + (size_t)n0 * DT;   // p rows

    float acc[4][4][4]; ZERO_ACC(acc);
    const int NIT = DT / 32;   // 16
    load_h(smu, Ap, DT, tid);            load_h(smu + TSZ, Bp, DT, tid);            cpc();
    load_h(smu + STG, Ap + 32, DT, tid); load_h(smu + STG + TSZ, Bp + 32, DT, tid); cpc();
    int sc = 0, sl = 2;
    for (int i = 0; i < NIT; i++) {
        cpw1(); __syncthreads();
        if (i + 2 < NIT) {
            load_h(smu + sl * STG, Ap + (i + 2) * 32, DT, tid);
            load_h(smu + sl * STG + TSZ, Bp + (i + 2) * 32, DT, tid);
        }
        cpc();
        comp_ebf(smu + sc * STG, smu + sc * STG + TSZ, acc, wm, wn, g, tig);
        sc = (sc == 2) ? 0 : sc + 1; sl = (sl == 2) ? 0 : sl + 1;
    }

    __half* Ep = g_E + (size_t)bh * P_ * P_;
#pragma unroll
    for (int mi = 0; mi < 4; mi++) {
        int q = m0 + wm * 64 + mi * 16 + g;
#pragma unroll
        for (int ni = 0; ni < 4; ni++) {
            int p = n0 + wn * 32 + ni * 8 + 2 * tig;
            *(__half2*)(Ep + (size_t)q * P_ + p) =
                __floats2half2_rn(__expf(acc[mi][ni][0] * INVS), __expf(acc[mi][ni][1] * INVS));
            *(__half2*)(Ep + (size_t)(q + 8) * P_ + p) =
                __floats2half2_rn(__expf(acc[mi][ni][2] * INVS), __expf(acc[mi][ni][3] * INVS));
        }
    }
}

// ---------------------------------------------------------------------------
// colsum: g_S[bh][p] = 1 / sum_q g_E[bh][q][p]   (coalesced column reduce)
// ---------------------------------------------------------------------------
__global__ __launch_bounds__(256) void colsum_kernel() {
    int bh = blockIdx.y, p0 = blockIdx.x * 512;
    int t = threadIdx.x;
    const __half2* base = (const __half2*)(g_E + (size_t)bh * P_ * P_ + p0) + t;
    float2 s = make_float2(0.f, 0.f);
#pragma unroll 8
    for (int q = 0; q < P_; q++) {
        float2 f = __half22float2(base[q * (P_ / 2)]);
        s.x += f.x; s.y += f.y;
    }
    float* Sp = g_S + (size_t)bh * P_ + p0 + 2 * t;
    Sp[0] = 1.0f / s.x;
    Sp[1] = 1.0f / s.y;
}

// ---------------------------------------------------------------------------
// vscale: V'[p][dt] *= invS[p]   (fold softmax denominator into V)
// g_Vh layout [bh][p/2][dt][2]: each uint4 = 4 half2, each half2 = (p even, p odd)
// ---------------------------------------------------------------------------
__global__ __launch_bounds__(256) void vscale_kernel() {
    size_t id = (size_t)blockIdx.x * 256 + threadIdx.x;   // over uint4 units
    size_t bhpp = id >> 7;            // 128 uint4 per (bh, p-pair)
    int within = (int)(id & 127);
    int bh = (int)(bhpp >> 9);        // 512 pairs per bh
    int pp = (int)(bhpp & 511);
    float s0 = g_S[(size_t)bh * P_ + 2 * pp];
    float s1 = g_S[(size_t)bh * P_ + 2 * pp + 1];
    __half2 sc = __floats2half2_rn(s0, s1);
    uint4* ptr = (uint4*)g_Vh + bhpp * 128 + within;
    uint4 u = *ptr;
    __half2* hp = (__half2*)&u;
#pragma unroll
    for (int j = 0; j < 4; j++) hp[j] = __hmul2(hp[j], sc);
    *ptr = u;
}

// ---------------------------------------------------------------------------
// av: out[q][dt] = sum_p exp[q][p] V'[p][dt]   (fp16 mma, 3-stage)
// ---------------------------------------------------------------------------
__global__ __launch_bounds__(256) void av_kernel(float* __restrict__ out) {
    extern __shared__ unsigned smu[];
    const int ATSZ = 128 * SEW;   // 2560 words
    const int BTSZ = 16 * SBV;    // 2176 words
    const int STG = ATSZ + BTSZ;  // 4736 words
    int tid = threadIdx.x, lane = tid & 31, warp = tid >> 5;
    int g = lane >> 2, tig = lane & 3, wm = warp >> 2, wn = warp & 3;
    int bh = blockIdx.z, b = bh >> 3, h = bh & 7;
    int m0 = blockIdx.y * 128;   // q
    int n0 = blockIdx.x * 128;   // dt
    const __half* Ap = g_E + ((size_t)bh * P_ + m0) * P_;             // rows q, cols p
    const __half* Bp = g_Vh + (size_t)bh * P_ * DT + (size_t)n0 * 2;  // kpair rows

    float acc[4][4][4]; ZERO_ACC(acc);
    const int NIT = P_ / 32;   // 32
    load_h(smu, Ap, P_, tid);                         load_v(smu + ATSZ, Bp, tid);                          cpc();
    load_h(smu + STG, Ap + 32, P_, tid);              load_v(smu + STG + ATSZ, Bp + 16 * (DT * 2), tid);    cpc();
    int sc = 0, sl = 2;
    for (int i = 0; i < NIT; i++) {
        cpw1(); __syncthreads();
        if (i + 2 < NIT) {
            load_h(smu + sl * STG, Ap + (i + 2) * 32, P_, tid);
            load_v(smu + sl * STG + ATSZ, Bp + (size_t)(i + 2) * 16 * (DT * 2), tid);
        }
        cpc();
        comp_av2(smu + sc * STG, smu + sc * STG + ATSZ, acc, wm, wn, g, tig);
        sc = (sc == 2) ? 0 : sc + 1; sl = (sl == 2) ? 0 : sl + 1;
    }

#pragma unroll
    for (int mi = 0; mi < 4; mi++)
#pragma unroll
        for (int half_ = 0; half_ < 2; half_++) {
            int q = m0 + wm * 64 + mi * 16 + g + half_ * 8;
#pragma unroll
            for (int ni = 0; ni < 4; ni++) {
                int n = n0 + wn * 32 + ni * 8 + 2 * tig;
                int d = n >> 4, t = n & 15;
                float2 v = make_float2(acc[mi][ni][2 * half_], acc[mi][ni][2 * half_ + 1]);
                *(float2*)(out + (((size_t)b * C_ + h * 32 + d) * P_ + q) * T_ + t) = v;
            }
        }
}

// ---------------------------------------------------------------------------
extern "C" void kernel_launch(void* const* d_in, const int* in_sizes, int n_in,
                              void* d_out, int out_size) {
    const float* x  = (const float*)d_in[0];
    const float* Wk = (const float*)d_in[1];
    const float* Wq = (const float*)d_in[2];
    const float* Wv = (const float*)d_in[3];
    float* out = (float*)d_out;

    const int SM_PROJ = 3 * (4608 + 4352) * 4;               // 107520
    const int SM_EN   = 3 * 2 * 128 * SEW * 4;               // 61440
    const int SM_AV   = 3 * (128 * SEW + 16 * SBV) * 4;      // 56832
    cudaFuncSetAttribute(proj_kernel,   cudaFuncAttributeMaxDynamicSharedMemorySize, SM_PROJ);
    cudaFuncSetAttribute(energy_kernel, cudaFuncAttributeMaxDynamicSharedMemorySize, SM_EN);
    cudaFuncSetAttribute(av_kernel,     cudaFuncAttributeMaxDynamicSharedMemorySize, SM_AV);

    proj_kernel<<<dim3(PT / 128, C_ / 128, 3 * B_), 256, SM_PROJ>>>(x, Wk, Wq, Wv);
    energy_kernel<<<dim3(P_ / 128, P_ / 128, BH), 256, SM_EN>>>();
    colsum_kernel<<<dim3(P_ / 512, BH), 256>>>();
    vscale_kernel<<<(BH * (P_ / 2) * DT / 4) / 256, 256>>>();
    av_kernel<<<dim3(DT / 128, P_ / 128, BH), 256, SM_AV>>>(out);
}

// round 10
// speedup vs baseline: 1.7343x; 1.1476x over previous
#include <cuda_runtime.h>
#include <cuda_bf16.h>
#include <cuda_fp16.h>

#define B_  8
#define C_  256
#define P_  1024
#define T_  16
#define DT  512      // D*T
#define PT  16384    // P*T
#define BH  64

// Scratch
__device__ __nv_bfloat16 g_K[(size_t)BH * P_ * DT];  // [bh][p][dt] bf16
__device__ __nv_bfloat16 g_Q[(size_t)BH * P_ * DT];  // [bh][p][dt] bf16
__device__ __half g_Vh[(size_t)BH * P_ * DT];        // [bh][p/2][dt][2] fp16 (p-pair interleaved)
__device__ __half g_E[(size_t)BH * P_ * P_];         // [bh][q][p] fp16 = exp(energy/sqrt(512))
__device__ float  g_Sp[(size_t)BH * 8 * P_];         // per-mblock partial colsums
__device__ float  g_S[(size_t)BH * P_];              // 1/colsum

#define SA 36     // proj row-k stride (words)
#define ST 136    // proj k-major stride (words)
#define SEW 20    // fp16/bf16 row-k stride: 128 rows x 32 elems (words)
#define SBV 136   // av B tile word stride: 16 kpair rows x 128 dt-words
#define NTHR 256
#define INVS 0.044194173824159216f   // 1/sqrt(512)

__device__ __forceinline__ unsigned f2tf(float f) {
    unsigned u; asm("cvt.rna.tf32.f32 %0, %1;" : "=r"(u) : "f"(f)); return u;
}

__device__ __forceinline__ void mma8(float* c, unsigned a0, unsigned a1, unsigned a2, unsigned a3,
                                     unsigned b0, unsigned b1) {
    asm volatile(
        "mma.sync.aligned.m16n8k8.row.col.f32.tf32.tf32.f32 "
        "{%0,%1,%2,%3},{%4,%5,%6,%7},{%8,%9},{%0,%1,%2,%3};"
        : "+f"(c[0]), "+f"(c[1]), "+f"(c[2]), "+f"(c[3])
        : "r"(a0), "r"(a1), "r"(a2), "r"(a3), "r"(b0), "r"(b1));
}
__device__ __forceinline__ void mmabf(float* c, unsigned a0, unsigned a1, unsigned a2, unsigned a3,
                                      unsigned b0, unsigned b1) {
    asm volatile(
        "mma.sync.aligned.m16n8k16.row.col.f32.bf16.bf16.f32 "
        "{%0,%1,%2,%3},{%4,%5,%6,%7},{%8,%9},{%0,%1,%2,%3};"
        : "+f"(c[0]), "+f"(c[1]), "+f"(c[2]), "+f"(c[3])
        : "r"(a0), "r"(a1), "r"(a2), "r"(a3), "r"(b0), "r"(b1));
}
__device__ __forceinline__ void mmah(float* c, unsigned a0, unsigned a1, unsigned a2, unsigned a3,
                                     unsigned b0, unsigned b1) {
    asm volatile(
        "mma.sync.aligned.m16n8k16.row.col.f32.f16.f16.f32 "
        "{%0,%1,%2,%3},{%4,%5,%6,%7},{%8,%9},{%0,%1,%2,%3};"
        : "+f"(c[0]), "+f"(c[1]), "+f"(c[2]), "+f"(c[3])
        : "r"(a0), "r"(a1), "r"(a2), "r"(a3), "r"(b0), "r"(b1));
}
__device__ __forceinline__ void ldsm4(unsigned& r0, unsigned& r1, unsigned& r2, unsigned& r3,
                                      unsigned addr) {
    asm volatile("ldmatrix.sync.aligned.m8n8.x4.shared.b16 {%0,%1,%2,%3}, [%4];"
        : "=r"(r0), "=r"(r1), "=r"(r2), "=r"(r3) : "r"(addr));
}
__device__ __forceinline__ void cp16(void* s, const void* g) {
    unsigned a = (unsigned)__cvta_generic_to_shared(s);
    asm volatile("cp.async.cg.shared.global [%0], [%1], 16;" :: "r"(a), "l"(g));
}
__device__ __forceinline__ void cpc()  { asm volatile("cp.async.commit_group;"); }
__device__ __forceinline__ void cpw1() { asm volatile("cp.async.wait_group 1;"); }

// ---- tile loaders ----
__device__ __forceinline__ void load_rk(float* buf, const float* g, int ldg, int tid) {
#pragma unroll
    for (int j = 0; j < 4; j++) {
        int c = tid + j * NTHR;
        int row = c >> 3, col = (c & 7) * 4;
        cp16(buf + row * SA + col, g + (size_t)row * ldg + col);
    }
}
__device__ __forceinline__ void load_t(float* buf, const float* g, int ldg, int tid) {
#pragma unroll
    for (int j = 0; j < 4; j++) {
        int c = tid + j * NTHR;
        int row = c >> 5, col = (c & 31) * 4;
        cp16(buf + row * ST + col, g + (size_t)row * ldg + col);
    }
}
// 128 rows x 32 16-bit elems (64B/row), row stride ldg (elems), smem stride SEW words
__device__ __forceinline__ void load_h(unsigned* buf, const void* gv, int ldg, int tid) {
    const __half* g = (const __half*)gv;
#pragma unroll
    for (int j = 0; j < 2; j++) {
        int c = tid + j * NTHR;
        int row = c >> 2, ch = c & 3;
        cp16(buf + row * SEW + ch * 4, g + (size_t)row * ldg + ch * 8);
    }
}
// av B: 16 kpair rows x 512B, gmem row stride DT*2 halfs
__device__ __forceinline__ void load_v(unsigned* buf, const __half* g, int tid) {
#pragma unroll
    for (int j = 0; j < 2; j++) {
        int c = tid + j * NTHR;
        int row = c >> 5, ch = c & 31;
        cp16(buf + row * SBV + ch * 4, g + (size_t)row * (DT * 2) + ch * 8);
    }
}

// ---- proj compute: A row-k (cvt), B k-major (cvt), tf32 ----
__device__ __forceinline__ void comp_rk_t(const float* As, const float* Bt, float acc[4][4][4],
                                          int wm, int wn, int g, int tig) {
#pragma unroll
    for (int kk = 0; kk < 4; kk++) {
        int k0 = kk * 8 + tig;
        unsigned a[4][4];
#pragma unroll
        for (int mi = 0; mi < 4; mi++) {
            int r = wm * 64 + mi * 16 + g;
            a[mi][0] = f2tf(As[r * SA + k0]);       a[mi][1] = f2tf(As[(r + 8) * SA + k0]);
            a[mi][2] = f2tf(As[r * SA + k0 + 4]);   a[mi][3] = f2tf(As[(r + 8) * SA + k0 + 4]);
        }
#pragma unroll
        for (int ni = 0; ni < 4; ni++) {
            int n = wn * 32 + ni * 8 + g;
            unsigned b0 = f2tf(Bt[k0 * ST + n]), b1 = f2tf(Bt[(k0 + 4) * ST + n]);
#pragma unroll
            for (int mi = 0; mi < 4; mi++)
                mma8(acc[mi][ni], a[mi][0], a[mi][1], a[mi][2], a[mi][3], b0, b1);
        }
    }
}

// ---- 16-bit GEMM compute via ldmatrix: both operands row-k, stride SEW ----
// A fragment x4: matrices [m0-7,k0-7],[m8-15,k0-7],[m0-7,k8-15],[m8-15,k8-15]
//   lane addr: row = m0 + (lane&15); +16B if lane>=16
// B fragment x4: matrices [n0-7,k0-7],[n0-7,k8-15],[n8-15,k0-7],[n8-15,k8-15]
//   lane addr: row = n0 + (lane&7) + ((lane>>4)<<3); +16B if (lane&8)
template<bool BF>
__device__ __forceinline__ void comp16(unsigned Au, unsigned Bu, float acc[4][4][4],
                                       int wm, int wn, int lane) {
    unsigned aBase = Au + (unsigned)((wm * 64 + (lane & 15)) * SEW * 4) + ((lane & 16) ? 16u : 0u);
    unsigned bBase = Bu + (unsigned)((wn * 32 + (lane & 7) + ((lane >> 4) << 3)) * SEW * 4)
                       + ((lane & 8) ? 16u : 0u);
#pragma unroll
    for (int c = 0; c < 2; c++) {
        unsigned co = c * 32;
        unsigned bb[4][2];
        ldsm4(bb[0][0], bb[0][1], bb[1][0], bb[1][1], bBase + co);
        ldsm4(bb[2][0], bb[2][1], bb[3][0], bb[3][1], bBase + 16 * SEW * 4 + co);
#pragma unroll
        for (int mi = 0; mi < 4; mi++) {
            unsigned a0, a1, a2, a3;
            ldsm4(a0, a1, a2, a3, aBase + mi * (16 * SEW * 4) + co);
#pragma unroll
            for (int ni = 0; ni < 4; ni++) {
                if (BF) mmabf(acc[mi][ni], a0, a1, a2, a3, bb[ni][0], bb[ni][1]);
                else    mmah (acc[mi][ni], a0, a1, a2, a3, bb[ni][0], bb[ni][1]);
            }
        }
    }
}

// ---- av compute: A via ldmatrix (stride SEW), B scalar kpair-major (stride SBV) ----
__device__ __forceinline__ void comp_av3(unsigned Au, const unsigned* Bt, float acc[4][4][4],
                                         int wm, int wn, int g, int tig, int lane) {
    unsigned aBase = Au + (unsigned)((wm * 64 + (lane & 15)) * SEW * 4) + ((lane & 16) ? 16u : 0u);
#pragma unroll
    for (int c = 0; c < 2; c++) {
        int w0 = c * 8 + tig;
        unsigned bb[4][2];
#pragma unroll
        for (int ni = 0; ni < 4; ni++) {
            int n = wn * 32 + ni * 8 + g;
            bb[ni][0] = Bt[w0 * SBV + n]; bb[ni][1] = Bt[(w0 + 4) * SBV + n];
        }
#pragma unroll
        for (int mi = 0; mi < 4; mi++) {
            unsigned a0, a1, a2, a3;
            ldsm4(a0, a1, a2, a3, aBase + mi * (16 * SEW * 4) + c * 32);
#pragma unroll
            for (int ni = 0; ni < 4; ni++)
                mmah(acc[mi][ni], a0, a1, a2, a3, bb[ni][0], bb[ni][1]);
        }
    }
}

#define ZERO_ACC(acc) \
    _Pragma("unroll") for (int mi = 0; mi < 4; mi++) \
    _Pragma("unroll") for (int ni = 0; ni < 4; ni++) \
    _Pragma("unroll") for (int e = 0; e < 4; e++) acc[mi][ni][e] = 0.f;

// ---------------------------------------------------------------------------
// proj: Y[o, pt] = sum_c W[o,c] x[b,c,pt]
// K,Q -> bf16 [p][dt]; V -> fp16 [p/2][dt][2]
// ---------------------------------------------------------------------------
__global__ __launch_bounds__(256) void proj_kernel(const float* __restrict__ x,
                                                   const float* __restrict__ Wk,
                                                   const float* __restrict__ Wq,
                                                   const float* __restrict__ Wv) {
    extern __shared__ float sm[];
    const int STG = 4608 + 4352;
    int tid = threadIdx.x, lane = tid & 31, warp = tid >> 5;
    int g = lane >> 2, tig = lane & 3, wm = warp >> 2, wn = warp & 3;
    int bz = blockIdx.z, w = bz % 3, b = bz / 3;
    const float* W = (w == 0) ? Wk : (w == 1) ? Wq : Wv;
    int m0 = blockIdx.y * 128, n0 = blockIdx.x * 128;
    const float* Ap = W + (size_t)m0 * C_;
    const float* Bp = x + (size_t)b * C_ * PT + n0;

    float acc[4][4][4]; ZERO_ACC(acc);
    const int NIT = C_ / 32;
    load_rk(sm, Ap, C_, tid);            load_t(sm + 4608, Bp, PT, tid);            cpc();
    load_rk(sm + STG, Ap + 32, C_, tid); load_t(sm + STG + 4608, Bp + 32 * PT, PT, tid); cpc();
    int sc = 0, sl = 2;
    for (int i = 0; i < NIT; i++) {
        cpw1(); __syncthreads();
        if (i + 2 < NIT) {
            load_rk(sm + sl * STG, Ap + (i + 2) * 32, C_, tid);
            load_t(sm + sl * STG + 4608, Bp + (size_t)(i + 2) * 32 * PT, PT, tid);
        }
        cpc();
        comp_rk_t(sm + sc * STG, sm + sc * STG + 4608, acc, wm, wn, g, tig);
        sc = (sc == 2) ? 0 : sc + 1; sl = (sl == 2) ? 0 : sl + 1;
    }

    if (w == 2) {
        // V: fp16, [bh][p/2][dt][2]
#pragma unroll
        for (int mi = 0; mi < 4; mi++)
#pragma unroll
            for (int half_ = 0; half_ < 2; half_++) {
                int o = m0 + wm * 64 + mi * 16 + g + half_ * 8;
                int h = o >> 5, d = o & 31;
                size_t base = ((size_t)(b * 8 + h)) * (P_ / 2);
#pragma unroll
                for (int ni = 0; ni < 4; ni++)
#pragma unroll
                    for (int e = 0; e < 2; e++) {
                        int col = n0 + wn * 32 + ni * 8 + 2 * tig + e;
                        int p = col >> 4, t = col & 15;
                        size_t idx = (base + (p >> 1)) * (size_t)(DT * 2) + (d * 16 + t) * 2 + (p & 1);
                        g_Vh[idx] = __float2half(acc[mi][ni][2 * half_ + e]);
                    }
            }
    } else {
        __nv_bfloat16* dst = (w == 0) ? g_K : g_Q;
#pragma unroll
        for (int mi = 0; mi < 4; mi++)
#pragma unroll
            for (int half_ = 0; half_ < 2; half_++) {
                int o = m0 + wm * 64 + mi * 16 + g + half_ * 8;
                int h = o >> 5, d = o & 31;
                size_t base = ((size_t)(b * 8 + h)) * P_;
#pragma unroll
                for (int ni = 0; ni < 4; ni++) {
                    int col = n0 + wn * 32 + ni * 8 + 2 * tig;
                    int p = col >> 4, t = col & 15;
                    __nv_bfloat162 v = __floats2bfloat162_rn(acc[mi][ni][2 * half_],
                                                             acc[mi][ni][2 * half_ + 1]);
                    *(__nv_bfloat162*)(dst + (base + p) * DT + d * 16 + t) = v;
                }
            }
    }
}

// ---------------------------------------------------------------------------
// energy (pre-transposed + exp fused + partial colsums):
//   g_E[bh][q][p] = exp( (sum_dt Q[q][dt] K[p][dt]) / sqrt(512) )  fp16
//   g_Sp[bh][m0blk][p] = partial column sums over this block's 128 q
// ---------------------------------------------------------------------------
__global__ __launch_bounds__(256) void energy_kernel() {
    extern __shared__ unsigned smu[];
    const int TSZ = 128 * SEW;     // 2560 words
    const int STG = 2 * TSZ;
    int tid = threadIdx.x, lane = tid & 31, warp = tid >> 5;
    int g = lane >> 2, tig = lane & 3, wm = warp >> 2, wn = warp & 3;
    int bh = blockIdx.z, m0 = blockIdx.y * 128, n0 = blockIdx.x * 128;
    const __nv_bfloat16* Ap = g_Q + (size_t)bh * P_ * DT + (size_t)m0 * DT;   // q rows
    const __nv_bfloat16* Bp = g_K + (size_t)bh * P_ * DT + (size_t)n0 * DT;   // p rows

    float acc[4][4][4]; ZERO_ACC(acc);
    const int NIT = DT / 32;   // 16
    load_h(smu, Ap, DT, tid);            load_h(smu + TSZ, Bp, DT, tid);            cpc();
    load_h(smu + STG, Ap + 32, DT, tid); load_h(smu + STG + TSZ, Bp + 32, DT, tid); cpc();
    int sc = 0, sl = 2;
    for (int i = 0; i < NIT; i++) {
        cpw1(); __syncthreads();
        if (i + 2 < NIT) {
            load_h(smu + sl * STG, Ap + (i + 2) * 32, DT, tid);
            load_h(smu + sl * STG + TSZ, Bp + (i + 2) * 32, DT, tid);
        }
        cpc();
        unsigned Au = (unsigned)__cvta_generic_to_shared(smu + sc * STG);
        comp16<true>(Au, Au + TSZ * 4, acc, wm, wn, lane);
        sc = (sc == 2) ? 0 : sc + 1; sl = (sl == 2) ? 0 : sl + 1;
    }

    __half* Ep = g_E + (size_t)bh * P_ * P_;
    float ps[4][2];
#pragma unroll
    for (int ni = 0; ni < 4; ni++) { ps[ni][0] = 0.f; ps[ni][1] = 0.f; }
#pragma unroll
    for (int mi = 0; mi < 4; mi++) {
        int q = m0 + wm * 64 + mi * 16 + g;
#pragma unroll
        for (int ni = 0; ni < 4; ni++) {
            int p = n0 + wn * 32 + ni * 8 + 2 * tig;
            float e0 = __expf(acc[mi][ni][0] * INVS), e1 = __expf(acc[mi][ni][1] * INVS);
            float e2 = __expf(acc[mi][ni][2] * INVS), e3 = __expf(acc[mi][ni][3] * INVS);
            *(__half2*)(Ep + (size_t)q * P_ + p)       = __floats2half2_rn(e0, e1);
            *(__half2*)(Ep + (size_t)(q + 8) * P_ + p) = __floats2half2_rn(e2, e3);
            ps[ni][0] += e0 + e2;
            ps[ni][1] += e1 + e3;
        }
    }
    // stage partial sums: [p_local 0..127][slot 0..15], stride 17
    __syncthreads();
    float* red = (float*)smu;
#pragma unroll
    for (int ni = 0; ni < 4; ni++)
#pragma unroll
        for (int e = 0; e < 2; e++) {
            int pl = wn * 32 + ni * 8 + 2 * tig + e;
            red[pl * 17 + wm * 8 + g] = ps[ni][e];
        }
    __syncthreads();
    if (tid < 128) {
        float s = 0.f;
#pragma unroll
        for (int k = 0; k < 16; k++) s += red[tid * 17 + k];
        g_Sp[((size_t)bh * 8 + blockIdx.y) * P_ + n0 + tid] = s;
    }
}

// ---------------------------------------------------------------------------
// sreduce: g_S[bh][p] = 1 / sum_m g_Sp[bh][m][p]
// ---------------------------------------------------------------------------
__global__ __launch_bounds__(1024) void sreduce_kernel() {
    int bh = blockIdx.x, p = threadIdx.x;
    float s = 0.f;
#pragma unroll
    for (int m = 0; m < 8; m++) s += g_Sp[((size_t)bh * 8 + m) * P_ + p];
    g_S[(size_t)bh * P_ + p] = 1.0f / s;
}

// ---------------------------------------------------------------------------
// vscale: V'[p][dt] *= invS[p]
// ---------------------------------------------------------------------------
__global__ __launch_bounds__(256) void vscale_kernel() {
    size_t id = (size_t)blockIdx.x * 256 + threadIdx.x;
    size_t bhpp = id >> 7;
    int within = (int)(id & 127);
    int bh = (int)(bhpp >> 9);
    int pp = (int)(bhpp & 511);
    float s0 = g_S[(size_t)bh * P_ + 2 * pp];
    float s1 = g_S[(size_t)bh * P_ + 2 * pp + 1];
    __half2 sc = __floats2half2_rn(s0, s1);
    uint4* ptr = (uint4*)g_Vh + bhpp * 128 + within;
    uint4 u = *ptr;
    __half2* hp = (__half2*)&u;
#pragma unroll
    for (int j = 0; j < 4; j++) hp[j] = __hmul2(hp[j], sc);
    *ptr = u;
}

// ---------------------------------------------------------------------------
// av: out[q][dt] = sum_p exp[q][p] V'[p][dt]   (fp16 mma, ldmatrix A, 3-stage)
// ---------------------------------------------------------------------------
__global__ __launch_bounds__(256) void av_kernel(float* __restrict__ out) {
    extern __shared__ unsigned smu[];
    const int ATSZ = 128 * SEW;   // 2560 words
    const int BTSZ = 16 * SBV;    // 2176 words
    const int STG = ATSZ + BTSZ;  // 4736 words
    int tid = threadIdx.x, lane = tid & 31, warp = tid >> 5;
    int g = lane >> 2, tig = lane & 3, wm = warp >> 2, wn = warp & 3;
    int bh = blockIdx.z, b = bh >> 3, h = bh & 7;
    int m0 = blockIdx.y * 128;   // q
    int n0 = blockIdx.x * 128;   // dt
    const __half* Ap = g_E + ((size_t)bh * P_ + m0) * P_;
    const __half* Bp = g_Vh + (size_t)bh * P_ * DT + (size_t)n0 * 2;

    float acc[4][4][4]; ZERO_ACC(acc);
    const int NIT = P_ / 32;   // 32
    load_h(smu, Ap, P_, tid);             load_v(smu + ATSZ, Bp, tid);                       cpc();
    load_h(smu + STG, Ap + 32, P_, tid);  load_v(smu + STG + ATSZ, Bp + 16 * (DT * 2), tid); cpc();
    int sc = 0, sl = 2;
    for (int i = 0; i < NIT; i++) {
        cpw1(); __syncthreads();
        if (i + 2 < NIT) {
            load_h(smu + sl * STG, Ap + (i + 2) * 32, P_, tid);
            load_v(smu + sl * STG + ATSZ, Bp + (size_t)(i + 2) * 16 * (DT * 2), tid);
        }
        cpc();
        unsigned Au = (unsigned)__cvta_generic_to_shared(smu + sc * STG);
        comp_av3(Au, smu + sc * STG + ATSZ, acc, wm, wn, g, tig, lane);
        sc = (sc == 2) ? 0 : sc + 1; sl = (sl == 2) ? 0 : sl + 1;
    }

#pragma unroll
    for (int mi = 0; mi < 4; mi++)
#pragma unroll
        for (int half_ = 0; half_ < 2; half_++) {
            int q = m0 + wm * 64 + mi * 16 + g + half_ * 8;
#pragma unroll
            for (int ni = 0; ni < 4; ni++) {
                int n = n0 + wn * 32 + ni * 8 + 2 * tig;
                int d = n >> 4, t = n & 15;
                float2 v = make_float2(acc[mi][ni][2 * half_], acc[mi][ni][2 * half_ + 1]);
                *(float2*)(out + (((size_t)b * C_ + h * 32 + d) * P_ + q) * T_ + t) = v;
            }
        }
}

// ---------------------------------------------------------------------------
extern "C" void kernel_launch(void* const* d_in, const int* in_sizes, int n_in,
                              void* d_out, int out_size) {
    const float* x  = (const float*)d_in[0];
    const float* Wk = (const float*)d_in[1];
    const float* Wq = (const float*)d_in[2];
    const float* Wv = (const float*)d_in[3];
    float* out = (float*)d_out;

    const int SM_PROJ = 3 * (4608 + 4352) * 4;               // 107520
    const int SM_EN   = 3 * 2 * 128 * SEW * 4;               // 61440
    const int SM_AV   = 3 * (128 * SEW + 16 * SBV) * 4;      // 56832
    cudaFuncSetAttribute(proj_kernel,   cudaFuncAttributeMaxDynamicSharedMemorySize, SM_PROJ);
    cudaFuncSetAttribute(energy_kernel, cudaFuncAttributeMaxDynamicSharedMemorySize, SM_EN);
    cudaFuncSetAttribute(av_kernel,     cudaFuncAttributeMaxDynamicSharedMemorySize, SM_AV);

    proj_kernel<<<dim3(PT / 128, C_ / 128, 3 * B_), 256, SM_PROJ>>>(x, Wk, Wq, Wv);
    energy_kernel<<<dim3(P_ / 128, P_ / 128, BH), 256, SM_EN>>>();
    sreduce_kernel<<<BH, 1024>>>();
    vscale_kernel<<<(BH * (P_ / 2) * DT / 4) / 256, 256>>>();
    av_kernel<<<dim3(DT / 128, P_ / 128, BH), 256, SM_AV>>>(out);
}

// round 12
// speedup vs baseline: 1.9985x; 1.1523x over previous
#include <cuda_runtime.h>
#include <cuda_fp16.h>

#define B_  8
#define C_  256
#define P_  1024
#define T_  16
#define DT  512      // D*T
#define PT  16384    // P*T
#define BH  64

// Scratch
__device__ __half g_Xt[(size_t)B_ * PT * C_];   // [b][pt][c] fp16 (transposed x)
__device__ __half g_Wh[3 * C_ * C_];            // [w][o][c] fp16
__device__ __half g_K[(size_t)BH * P_ * DT];    // [bh][p][dt] fp16
__device__ __half g_Q[(size_t)BH * P_ * DT];    // [bh][p][dt] fp16
__device__ __half g_Vh[(size_t)BH * P_ * DT];   // [bh][p/2][dt][2] fp16 (p-pair interleaved)
__device__ __half g_E[(size_t)BH * P_ * P_];    // [bh][q][p] fp16 = exp(energy/sqrt(512))
__device__ float  g_Sp[(size_t)BH * 8 * P_];    // per-mblock partial colsums
__device__ float  g_S[(size_t)BH * P_];         // 1/colsum

#define SEW 20    // fp16 row-k stride: 128 rows x 32 elems (32-bit words)
#define SBV 136   // av B tile word stride: 16 kpair rows x 128 dt-words
#define NTHR 256
#define INVS 0.044194173824159216f   // 1/sqrt(512)

__device__ __forceinline__ void mmah(float* c, unsigned a0, unsigned a1, unsigned a2, unsigned a3,
                                     unsigned b0, unsigned b1) {
    asm volatile(
        "mma.sync.aligned.m16n8k16.row.col.f32.f16.f16.f32 "
        "{%0,%1,%2,%3},{%4,%5,%6,%7},{%8,%9},{%0,%1,%2,%3};"
        : "+f"(c[0]), "+f"(c[1]), "+f"(c[2]), "+f"(c[3])
        : "r"(a0), "r"(a1), "r"(a2), "r"(a3), "r"(b0), "r"(b1));
}
__device__ __forceinline__ void ldsm4(unsigned& r0, unsigned& r1, unsigned& r2, unsigned& r3,
                                      unsigned addr) {
    asm volatile("ldmatrix.sync.aligned.m8n8.x4.shared.b16 {%0,%1,%2,%3}, [%4];"
        : "=r"(r0), "=r"(r1), "=r"(r2), "=r"(r3) : "r"(addr));
}
__device__ __forceinline__ void cp16(void* s, const void* g) {
    unsigned a = (unsigned)__cvta_generic_to_shared(s);
    asm volatile("cp.async.cg.shared.global [%0], [%1], 16;" :: "r"(a), "l"(g));
}
__device__ __forceinline__ void cpc()  { asm volatile("cp.async.commit_group;"); }
__device__ __forceinline__ void cpw1() { asm volatile("cp.async.wait_group 1;"); }

// ---- tile loaders ----
// 128 rows x 32 fp16 (64B/row), gmem row stride ldg (elems), smem stride SEW words
__device__ __forceinline__ void load_h(unsigned* buf, const void* gv, int ldg, int tid) {
    const __half* g = (const __half*)gv;
#pragma unroll
    for (int j = 0; j < 2; j++) {
        int c = tid + j * NTHR;
        int row = c >> 2, ch = c & 3;
        cp16(buf + row * SEW + ch * 4, g + (size_t)row * ldg + ch * 8);
    }
}
// av B: 16 kpair rows x 512B, gmem row stride DT*2 halfs
__device__ __forceinline__ void load_v(unsigned* buf, const __half* g, int tid) {
#pragma unroll
    for (int j = 0; j < 2; j++) {
        int c = tid + j * NTHR;
        int row = c >> 5, ch = c & 31;
        cp16(buf + row * SBV + ch * 4, g + (size_t)row * (DT * 2) + ch * 8);
    }
}

// ---- fp16 GEMM compute via ldmatrix: both operands row-k, stride SEW ----
__device__ __forceinline__ void comp16(unsigned Au, unsigned Bu, float acc[4][4][4],
                                       int wm, int wn, int lane) {
    unsigned aBase = Au + (unsigned)((wm * 64 + (lane & 15)) * SEW * 4) + ((lane & 16) ? 16u : 0u);
    unsigned bBase = Bu + (unsigned)((wn * 32 + (lane & 7) + ((lane >> 4) << 3)) * SEW * 4)
                       + ((lane & 8) ? 16u : 0u);
#pragma unroll
    for (int c = 0; c < 2; c++) {
        unsigned co = c * 32;
        unsigned bb[4][2];
        ldsm4(bb[0][0], bb[0][1], bb[1][0], bb[1][1], bBase + co);
        ldsm4(bb[2][0], bb[2][1], bb[3][0], bb[3][1], bBase + 16 * SEW * 4 + co);
#pragma unroll
        for (int mi = 0; mi < 4; mi++) {
            unsigned a0, a1, a2, a3;
            ldsm4(a0, a1, a2, a3, aBase + mi * (16 * SEW * 4) + co);
#pragma unroll
            for (int ni = 0; ni < 4; ni++)
                mmah(acc[mi][ni], a0, a1, a2, a3, bb[ni][0], bb[ni][1]);
        }
    }
}

// ---- av compute: A via ldmatrix (stride SEW), B scalar kpair-major (stride SBV) ----
__device__ __forceinline__ void comp_av3(unsigned Au, const unsigned* Bt, float acc[4][4][4],
                                         int wm, int wn, int g, int tig, int lane) {
    unsigned aBase = Au + (unsigned)((wm * 64 + (lane & 15)) * SEW * 4) + ((lane & 16) ? 16u : 0u);
#pragma unroll
    for (int c = 0; c < 2; c++) {
        int w0 = c * 8 + tig;
        unsigned bb[4][2];
#pragma unroll
        for (int ni = 0; ni < 4; ni++) {
            int n = wn * 32 + ni * 8 + g;
            bb[ni][0] = Bt[w0 * SBV + n]; bb[ni][1] = Bt[(w0 + 4) * SBV + n];
        }
#pragma unroll
        for (int mi = 0; mi < 4; mi++) {
            unsigned a0, a1, a2, a3;
            ldsm4(a0, a1, a2, a3, aBase + mi * (16 * SEW * 4) + c * 32);
#pragma unroll
            for (int ni = 0; ni < 4; ni++)
                mmah(acc[mi][ni], a0, a1, a2, a3, bb[ni][0], bb[ni][1]);
        }
    }
}

#define ZERO_ACC(acc) \
    _Pragma("unroll") for (int mi = 0; mi < 4; mi++) \
    _Pragma("unroll") for (int ni = 0; ni < 4; ni++) \
    _Pragma("unroll") for (int e = 0; e < 4; e++) acc[mi][ni][e] = 0.f;

// ---------------------------------------------------------------------------
// xprep: g_Xt[b][pt][c] = fp16(x[b][c][pt])   (transpose + convert)
// Each thread: one pt, 64 c-values (strided reads, contiguous 128B write).
// ---------------------------------------------------------------------------
__global__ __launch_bounds__(256) void xprep_kernel(const float* __restrict__ x) {
    int b = blockIdx.z, c0 = blockIdx.y * 64;
    int pt = blockIdx.x * 256 + threadIdx.x;
    const float* xp = x + ((size_t)b * C_ + c0) * PT + pt;
    __half h[64];
#pragma unroll
    for (int c = 0; c < 64; c++) h[c] = __float2half(xp[(size_t)c * PT]);
    __half* dst = g_Xt + ((size_t)b * PT + pt) * C_ + c0;
#pragma unroll
    for (int j = 0; j < 8; j++) ((uint4*)dst)[j] = ((const uint4*)h)[j];
}

// ---------------------------------------------------------------------------
// wprep: g_Wh[w][o][c] = fp16(W[o][c])
// ---------------------------------------------------------------------------
__global__ __launch_bounds__(256) void wprep_kernel(const float* __restrict__ Wk,
                                                    const float* __restrict__ Wq,
                                                    const float* __restrict__ Wv) {
    int w = blockIdx.y;
    const float* src = (w == 0) ? Wk : (w == 1) ? Wq : Wv;
    int id = blockIdx.x * 256 + threadIdx.x;       // float4 index
    float4 v = ((const float4*)src)[id];
    __half h[4] = {__float2half(v.x), __float2half(v.y), __float2half(v.z), __float2half(v.w)};
    ((uint2*)(g_Wh + (size_t)w * C_ * C_))[id] = *(const uint2*)h;
}

// ---------------------------------------------------------------------------
// proj (fp16 GEMM): Y[o][pt] = sum_c Wh[o][c] * Xt[pt][c]
// K,Q -> fp16 [p][dt]; V -> fp16 [p/2][dt][2]
// ---------------------------------------------------------------------------
__global__ __launch_bounds__(256) void proj_kernel() {
    extern __shared__ unsigned smu[];
    const int TSZ = 128 * SEW;     // 2560 words
    const int STG = 2 * TSZ;
    int tid = threadIdx.x, lane = tid & 31, warp = tid >> 5;
    int g = lane >> 2, tig = lane & 3, wm = warp >> 2, wn = warp & 3;
    int bz = blockIdx.z, w = bz % 3, b = bz / 3;
    int m0 = blockIdx.y * 128, n0 = blockIdx.x * 128;
    const __half* Ap = g_Wh + (size_t)w * C_ * C_ + (size_t)m0 * C_;
    const __half* Bp = g_Xt + ((size_t)b * PT + n0) * C_;

    float acc[4][4][4]; ZERO_ACC(acc);
    const int NIT = C_ / 32;   // 8
    load_h(smu, Ap, C_, tid);            load_h(smu + TSZ, Bp, C_, tid);            cpc();
    load_h(smu + STG, Ap + 32, C_, tid); load_h(smu + STG + TSZ, Bp + 32, C_, tid); cpc();
    int sc = 0, sl = 2;
    for (int i = 0; i < NIT; i++) {
        cpw1(); __syncthreads();
        if (i + 2 < NIT) {
            load_h(smu + sl * STG, Ap + (i + 2) * 32, C_, tid);
            load_h(smu + sl * STG + TSZ, Bp + (i + 2) * 32, C_, tid);
        }
        cpc();
        unsigned Au = (unsigned)__cvta_generic_to_shared(smu + sc * STG);
        comp16(Au, Au + TSZ * 4, acc, wm, wn, lane);
        sc = (sc == 2) ? 0 : sc + 1; sl = (sl == 2) ? 0 : sl + 1;
    }

    if (w == 2) {
        // V: fp16, [bh][p/2][dt][2]
#pragma unroll
        for (int mi = 0; mi < 4; mi++)
#pragma unroll
            for (int half_ = 0; half_ < 2; half_++) {
                int o = m0 + wm * 64 + mi * 16 + g + half_ * 8;
                int h = o >> 5, d = o & 31;
                size_t base = ((size_t)(b * 8 + h)) * (P_ / 2);
#pragma unroll
                for (int ni = 0; ni < 4; ni++)
#pragma unroll
                    for (int e = 0; e < 2; e++) {
                        int col = n0 + wn * 32 + ni * 8 + 2 * tig + e;
                        int p = col >> 4, t = col & 15;
                        size_t idx = (base + (p >> 1)) * (size_t)(DT * 2) + (d * 16 + t) * 2 + (p & 1);
                        g_Vh[idx] = __float2half(acc[mi][ni][2 * half_ + e]);
                    }
            }
    } else {
        __half* dst = (w == 0) ? g_K : g_Q;
#pragma unroll
        for (int mi = 0; mi < 4; mi++)
#pragma unroll
            for (int half_ = 0; half_ < 2; half_++) {
                int o = m0 + wm * 64 + mi * 16 + g + half_ * 8;
                int h = o >> 5, d = o & 31;
                size_t base = ((size_t)(b * 8 + h)) * P_;
#pragma unroll
                for (int ni = 0; ni < 4; ni++) {
                    int col = n0 + wn * 32 + ni * 8 + 2 * tig;
                    int p = col >> 4, t = col & 15;
                    __half2 v = __floats2half2_rn(acc[mi][ni][2 * half_],
                                                  acc[mi][ni][2 * half_ + 1]);
                    *(__half2*)(dst + (base + p) * DT + d * 16 + t) = v;
                }
            }
    }
}

// ---------------------------------------------------------------------------
// energy (pre-transposed + exp fused + partial colsums):
//   g_E[bh][q][p] = exp( (sum_dt Q[q][dt] K[p][dt]) / sqrt(512) )  fp16
//   g_Sp[bh][m0blk][p] = partial column sums over this block's 128 q
// ---------------------------------------------------------------------------
__global__ __launch_bounds__(256) void energy_kernel() {
    extern __shared__ unsigned smu[];
    const int TSZ = 128 * SEW;
    const int STG = 2 * TSZ;
    int tid = threadIdx.x, lane = tid & 31, warp = tid >> 5;
    int g = lane >> 2, tig = lane & 3, wm = warp >> 2, wn = warp & 3;
    int bh = blockIdx.z, m0 = blockIdx.y * 128, n0 = blockIdx.x * 128;
    const __half* Ap = g_Q + (size_t)bh * P_ * DT + (size_t)m0 * DT;   // q rows
    const __half* Bp = g_K + (size_t)bh * P_ * DT + (size_t)n0 * DT;   // p rows

    float acc[4][4][4]; ZERO_ACC(acc);
    const int NIT = DT / 32;   // 16
    load_h(smu, Ap, DT, tid);            load_h(smu + TSZ, Bp, DT, tid);            cpc();
    load_h(smu + STG, Ap + 32, DT, tid); load_h(smu + STG + TSZ, Bp + 32, DT, tid); cpc();
    int sc = 0, sl = 2;
    for (int i = 0; i < NIT; i++) {
        cpw1(); __syncthreads();
        if (i + 2 < NIT) {
            load_h(smu + sl * STG, Ap + (i + 2) * 32, DT, tid);
            load_h(smu + sl * STG + TSZ, Bp + (i + 2) * 32, DT, tid);
        }
        cpc();
        unsigned Au = (unsigned)__cvta_generic_to_shared(smu + sc * STG);
        comp16(Au, Au + TSZ * 4, acc, wm, wn, lane);
        sc = (sc == 2) ? 0 : sc + 1; sl = (sl == 2) ? 0 : sl + 1;
    }

    __half* Ep = g_E + (size_t)bh * P_ * P_;
    float ps[4][2];
#pragma unroll
    for (int ni = 0; ni < 4; ni++) { ps[ni][0] = 0.f; ps[ni][1] = 0.f; }
#pragma unroll
    for (int mi = 0; mi < 4; mi++) {
        int q = m0 + wm * 64 + mi * 16 + g;
#pragma unroll
        for (int ni = 0; ni < 4; ni++) {
            int p = n0 + wn * 32 + ni * 8 + 2 * tig;
            float e0 = __expf(acc[mi][ni][0] * INVS), e1 = __expf(acc[mi][ni][1] * INVS);
            float e2 = __expf(acc[mi][ni][2] * INVS), e3 = __expf(acc[mi][ni][3] * INVS);
            *(__half2*)(Ep + (size_t)q * P_ + p)       = __floats2half2_rn(e0, e1);
            *(__half2*)(Ep + (size_t)(q + 8) * P_ + p) = __floats2half2_rn(e2, e3);
            ps[ni][0] += e0 + e2;
            ps[ni][1] += e1 + e3;
        }
    }
    __syncthreads();
    float* red = (float*)smu;
#pragma unroll
    for (int ni = 0; ni < 4; ni++)
#pragma unroll
        for (int e = 0; e < 2; e++) {
            int pl = wn * 32 + ni * 8 + 2 * tig + e;
            red[pl * 17 + wm * 8 + g] = ps[ni][e];
        }
    __syncthreads();
    if (tid < 128) {
        float s = 0.f;
#pragma unroll
        for (int k = 0; k < 16; k++) s += red[tid * 17 + k];
        g_Sp[((size_t)bh * 8 + blockIdx.y) * P_ + n0 + tid] = s;
    }
}

// ---------------------------------------------------------------------------
// sreduce: g_S[bh][p] = 1 / sum_m g_Sp[bh][m][p]
// ---------------------------------------------------------------------------
__global__ __launch_bounds__(1024) void sreduce_kernel() {
    int bh = blockIdx.x, p = threadIdx.x;
    float s = 0.f;
#pragma unroll
    for (int m = 0; m < 8; m++) s += g_Sp[((size_t)bh * 8 + m) * P_ + p];
    g_S[(size_t)bh * P_ + p] = 1.0f / s;
}

// ---------------------------------------------------------------------------
// vscale: V'[p][dt] *= invS[p]
// ---------------------------------------------------------------------------
__global__ __launch_bounds__(256) void vscale_kernel() {
    size_t id = (size_t)blockIdx.x * 256 + threadIdx.x;
    size_t bhpp = id >> 7;
    int within = (int)(id & 127);
    int bh = (int)(bhpp >> 9);
    int pp = (int)(bhpp & 511);
    float s0 = g_S[(size_t)bh * P_ + 2 * pp];
    float s1 = g_S[(size_t)bh * P_ + 2 * pp + 1];
    __half2 sc = __floats2half2_rn(s0, s1);
    uint4* ptr = (uint4*)g_Vh + bhpp * 128 + within;
    uint4 u = *ptr;
    __half2* hp = (__half2*)&u;
#pragma unroll
    for (int j = 0; j < 4; j++) hp[j] = __hmul2(hp[j], sc);
    *ptr = u;
}

// ---------------------------------------------------------------------------
// av: out[q][dt] = sum_p exp[q][p] V'[p][dt]   (fp16 mma, ldmatrix A, 3-stage)
// ---------------------------------------------------------------------------
__global__ __launch_bounds__(256) void av_kernel(float* __restrict__ out) {
    extern __shared__ unsigned smu[];
    const int ATSZ = 128 * SEW;   // 2560 words
    const int BTSZ = 16 * SBV;    // 2176 words
    const int STG = ATSZ + BTSZ;
    int tid = threadIdx.x, lane = tid & 31, warp = tid >> 5;
    int g = lane >> 2, tig = lane & 3, wm = warp >> 2, wn = warp & 3;
    int bh = blockIdx.z, b = bh >> 3, h = bh & 7;
    int m0 = blockIdx.y * 128;   // q
    int n0 = blockIdx.x * 128;   // dt
    const __half* Ap = g_E + ((size_t)bh * P_ + m0) * P_;
    const __half* Bp = g_Vh + (size_t)bh * P_ * DT + (size_t)n0 * 2;

    float acc[4][4][4]; ZERO_ACC(acc);
    const int NIT = P_ / 32;   // 32
    load_h(smu, Ap, P_, tid);             load_v(smu + ATSZ, Bp, tid);                       cpc();
    load_h(smu + STG, Ap + 32, P_, tid);  load_v(smu + STG + ATSZ, Bp + 16 * (DT * 2), tid); cpc();
    int sc = 0, sl = 2;
    for (int i = 0; i < NIT; i++) {
        cpw1(); __syncthreads();
        if (i + 2 < NIT) {
            load_h(smu + sl * STG, Ap + (i + 2) * 32, P_, tid);
            load_v(smu + sl * STG + ATSZ, Bp + (size_t)(i + 2) * 16 * (DT * 2), tid);
        }
        cpc();
        unsigned Au = (unsigned)__cvta_generic_to_shared(smu + sc * STG);
        comp_av3(Au, smu + sc * STG + ATSZ, acc, wm, wn, g, tig, lane);
        sc = (sc == 2) ? 0 : sc + 1; sl = (sl == 2) ? 0 : sl + 1;
    }

#pragma unroll
    for (int mi = 0; mi < 4; mi++)
#pragma unroll
        for (int half_ = 0; half_ < 2; half_++) {
            int q = m0 + wm * 64 + mi * 16 + g + half_ * 8;
#pragma unroll
            for (int ni = 0; ni < 4; ni++) {
                int n = n0 + wn * 32 + ni * 8 + 2 * tig;
                int d = n >> 4, t = n & 15;
                float2 v = make_float2(acc[mi][ni][2 * half_], acc[mi][ni][2 * half_ + 1]);
                *(float2*)(out + (((size_t)b * C_ + h * 32 + d) * P_ + q) * T_ + t) = v;
            }
        }
}

// ---------------------------------------------------------------------------
extern "C" void kernel_launch(void* const* d_in, const int* in_sizes, int n_in,
                              void* d_out, int out_size) {
    const float* x  = (const float*)d_in[0];
    const float* Wk = (const float*)d_in[1];
    const float* Wq = (const float*)d_in[2];
    const float* Wv = (const float*)d_in[3];
    float* out = (float*)d_out;

    const int SM_16 = 3 * 2 * 128 * SEW * 4;             // 61440
    const int SM_AV = 3 * (128 * SEW + 16 * SBV) * 4;    // 56832
    cudaFuncSetAttribute(proj_kernel,   cudaFuncAttributeMaxDynamicSharedMemorySize, SM_16);
    cudaFuncSetAttribute(energy_kernel, cudaFuncAttributeMaxDynamicSharedMemorySize, SM_16);
    cudaFuncSetAttribute(av_kernel,     cudaFuncAttributeMaxDynamicSharedMemorySize, SM_AV);

    xprep_kernel<<<dim3(PT / 256, 4, B_), 256>>>(x);
    wprep_kernel<<<dim3(C_ * C_ / 4 / 256, 3), 256>>>(Wk, Wq, Wv);
    proj_kernel<<<dim3(PT / 128, C_ / 128, 3 * B_), 256, SM_16>>>();
    energy_kernel<<<dim3(P_ / 128, P_ / 128, BH), 256, SM_16>>>();
    sreduce_kernel<<<BH, 1024>>>();
    vscale_kernel<<<(BH * (P_ / 2) * DT / 4) / 256, 256>>>();
    av_kernel<<<dim3(DT / 128, P_ / 128, BH), 256, SM_AV>>>(out);
}

// round 15
// speedup vs baseline: 2.1420x; 1.0718x over previous
#include <cuda_runtime.h>
#include <cuda_fp16.h>
#include <cstdint>

#define B_  8
#define C_  256
#define P_  1024
#define T_  16
#define DT  512      // D*T
#define PT  16384    // P*T
#define BH  64

// Scratch
__device__ __half g_Xt[(size_t)B_ * PT * C_];   // [b][pt][c] fp16 (transposed x)
__device__ __half g_Wh[3 * C_ * C_];            // [w][o][c] fp16
__device__ __half g_K[(size_t)BH * P_ * DT];    // [bh][p][dt] fp16
__device__ __half g_Q[(size_t)BH * P_ * DT];    // [bh][p][dt] fp16
__device__ __half g_Vh[(size_t)BH * P_ * DT];   // [bh][p/2][dt][2] fp16 (p-pair interleaved)
__device__ __half g_E[(size_t)BH * P_ * P_];    // [bh][q][p] fp16 = exp(energy/sqrt(512))
__device__ float  g_Sp[(size_t)BH * 8 * P_];    // per-mblock partial colsums
__device__ float  g_S[(size_t)BH * P_];         // 1/colsum

#define SEW 20    // proj row-k stride: 128 rows x 32 halfs (words)
#define SE2 36    // energy/av row-k stride: 128 rows x 64 halfs (words)
#define SBV 136   // av B tile word stride (kpair rows x 128 dt-words)
#define NTHR 256
#define INVS 0.044194173824159216f   // 1/sqrt(512)

__device__ __forceinline__ void mmah(float* c, unsigned a0, unsigned a1, unsigned a2, unsigned a3,
                                     unsigned b0, unsigned b1) {
    asm volatile(
        "mma.sync.aligned.m16n8k16.row.col.f32.f16.f16.f32 "
        "{%0,%1,%2,%3},{%4,%5,%6,%7},{%8,%9},{%0,%1,%2,%3};"
        : "+f"(c[0]), "+f"(c[1]), "+f"(c[2]), "+f"(c[3])
        : "r"(a0), "r"(a1), "r"(a2), "r"(a3), "r"(b0), "r"(b1));
}
__device__ __forceinline__ void ldsm4(unsigned& r0, unsigned& r1, unsigned& r2, unsigned& r3,
                                      unsigned addr) {
    asm volatile("ldmatrix.sync.aligned.m8n8.x4.shared.b16 {%0,%1,%2,%3}, [%4];"
        : "=r"(r0), "=r"(r1), "=r"(r2), "=r"(r3) : "r"(addr));
}
__device__ __forceinline__ void cp16(void* s, const void* g) {
    unsigned a = (unsigned)__cvta_generic_to_shared(s);
    asm volatile("cp.async.cg.shared.global [%0], [%1], 16;" :: "r"(a), "l"(g));
}
__device__ __forceinline__ void cpc()  { asm volatile("cp.async.commit_group;"); }
__device__ __forceinline__ void cpw1() { asm volatile("cp.async.wait_group 1;"); }

// ---- tile loaders ----
// proj: 128 rows x 32 halfs, stride SEW
__device__ __forceinline__ void load_h(unsigned* buf, const void* gv, int ldg, int tid) {
    const __half* g = (const __half*)gv;
#pragma unroll
    for (int j = 0; j < 2; j++) {
        int c = tid + j * NTHR;
        int row = c >> 2, ch = c & 3;
        cp16(buf + row * SEW + ch * 4, g + (size_t)row * ldg + ch * 8);
    }
}
// energy/av A: 128 rows x 64 halfs, stride SE2
__device__ __forceinline__ void load_h64(unsigned* buf, const void* gv, int ldg, int tid) {
    const __half* g = (const __half*)gv;
#pragma unroll
    for (int j = 0; j < 4; j++) {
        int c = tid + j * NTHR;
        int row = c >> 3, ch = c & 7;
        cp16(buf + row * SE2 + ch * 4, g + (size_t)row * ldg + ch * 8);
    }
}
// av B: 32 kpair rows x 512B, gmem row stride DT*2 halfs
__device__ __forceinline__ void load_v64(unsigned* buf, const __half* g, int tid) {
#pragma unroll
    for (int j = 0; j < 4; j++) {
        int c = tid + j * NTHR;
        int row = c >> 5, ch = c & 31;
        cp16(buf + row * SBV + ch * 4, g + (size_t)row * (DT * 2) + ch * 8);
    }
}

// ---- proj compute (32-k chunk, stride SEW) ----
__device__ __forceinline__ void comp16(unsigned Au, unsigned Bu, float acc[4][4][4],
                                       int wm, int wn, int lane) {
    unsigned aBase = Au + (unsigned)((wm * 64 + (lane & 15)) * SEW * 4) + ((lane & 16) ? 16u : 0u);
    unsigned bBase = Bu + (unsigned)((wn * 32 + (lane & 7) + ((lane >> 4) << 3)) * SEW * 4)
                       + ((lane & 8) ? 16u : 0u);
#pragma unroll
    for (int c = 0; c < 2; c++) {
        unsigned co = c * 32;
        unsigned bb[4][2];
        ldsm4(bb[0][0], bb[0][1], bb[1][0], bb[1][1], bBase + co);
        ldsm4(bb[2][0], bb[2][1], bb[3][0], bb[3][1], bBase + 16 * SEW * 4 + co);
#pragma unroll
        for (int mi = 0; mi < 4; mi++) {
            unsigned a0, a1, a2, a3;
            ldsm4(a0, a1, a2, a3, aBase + mi * (16 * SEW * 4) + co);
#pragma unroll
            for (int ni = 0; ni < 4; ni++)
                mmah(acc[mi][ni], a0, a1, a2, a3, bb[ni][0], bb[ni][1]);
        }
    }
}

// ---- energy compute (64-k chunk, stride SE2, both operands ldmatrix) ----
__device__ __forceinline__ void comp16_64(unsigned Au, unsigned Bu, float acc[4][4][4],
                                          int wm, int wn, int lane) {
    unsigned aBase = Au + (unsigned)((wm * 64 + (lane & 15)) * SE2 * 4) + ((lane & 16) ? 16u : 0u);
    unsigned bBase = Bu + (unsigned)((wn * 32 + (lane & 7) + ((lane >> 4) << 3)) * SE2 * 4)
                       + ((lane & 8) ? 16u : 0u);
#pragma unroll
    for (int c = 0; c < 4; c++) {
        unsigned co = c * 32;
        unsigned bb[4][2];
        ldsm4(bb[0][0], bb[0][1], bb[1][0], bb[1][1], bBase + co);
        ldsm4(bb[2][0], bb[2][1], bb[3][0], bb[3][1], bBase + 16 * SE2 * 4 + co);
#pragma unroll
        for (int mi = 0; mi < 4; mi++) {
            unsigned a0, a1, a2, a3;
            ldsm4(a0, a1, a2, a3, aBase + mi * (16 * SE2 * 4) + co);
#pragma unroll
            for (int ni = 0; ni < 4; ni++)
                mmah(acc[mi][ni], a0, a1, a2, a3, bb[ni][0], bb[ni][1]);
        }
    }
}

// ---- av compute (64-k chunk): A ldmatrix (stride SE2), B scalar kpair-major ----
__device__ __forceinline__ void comp_av64(unsigned Au, const unsigned* Bt, float acc[4][4][4],
                                          int wm, int wn, int g, int tig, int lane) {
    unsigned aBase = Au + (unsigned)((wm * 64 + (lane & 15)) * SE2 * 4) + ((lane & 16) ? 16u : 0u);
#pragma unroll
    for (int c = 0; c < 4; c++) {
        int w0 = c * 8 + tig;
        unsigned bb[4][2];
#pragma unroll
        for (int ni = 0; ni < 4; ni++) {
            int n = wn * 32 + ni * 8 + g;
            bb[ni][0] = Bt[w0 * SBV + n]; bb[ni][1] = Bt[(w0 + 4) * SBV + n];
        }
#pragma unroll
        for (int mi = 0; mi < 4; mi++) {
            unsigned a0, a1, a2, a3;
            ldsm4(a0, a1, a2, a3, aBase + mi * (16 * SE2 * 4) + c * 32);
#pragma unroll
            for (int ni = 0; ni < 4; ni++)
                mmah(acc[mi][ni], a0, a1, a2, a3, bb[ni][0], bb[ni][1]);
        }
    }
}

#define ZERO_ACC(acc) \
    _Pragma("unroll") for (int mi = 0; mi < 4; mi++) \
    _Pragma("unroll") for (int ni = 0; ni < 4; ni++) \
    _Pragma("unroll") for (int e = 0; e < 4; e++) acc[mi][ni][e] = 0.f;

// ---------------------------------------------------------------------------
// xprep: g_Xt[b][pt][c] = fp16(x[b][c][pt])
// ---------------------------------------------------------------------------
__global__ __launch_bounds__(256) void xprep_kernel(const float* __restrict__ x) {
    int b = blockIdx.z, c0 = blockIdx.y * 64;
    int pt = blockIdx.x * 256 + threadIdx.x;
    const float* xp = x + ((size_t)b * C_ + c0) * PT + pt;
    __half h[64];
#pragma unroll
    for (int c = 0; c < 64; c++) h[c] = __float2half(xp[(size_t)c * PT]);
    __half* dst = g_Xt + ((size_t)b * PT + pt) * C_ + c0;
#pragma unroll
    for (int j = 0; j < 8; j++) ((uint4*)dst)[j] = ((const uint4*)h)[j];
}

// ---------------------------------------------------------------------------
// wprep: g_Wh[w][o][c] = fp16(W[o][c])
// ---------------------------------------------------------------------------
__global__ __launch_bounds__(256) void wprep_kernel(const float* __restrict__ Wk,
                                                    const float* __restrict__ Wq,
                                                    const float* __restrict__ Wv) {
    int w = blockIdx.y;
    const float* src = (w == 0) ? Wk : (w == 1) ? Wq : Wv;
    int id = blockIdx.x * 256 + threadIdx.x;
    float4 v = ((const float4*)src)[id];
    __half h[4] = {__float2half(v.x), __float2half(v.y), __float2half(v.z), __float2half(v.w)};
    ((uint2*)(g_Wh + (size_t)w * C_ * C_))[id] = *(const uint2*)h;
}

// ---------------------------------------------------------------------------
// proj (fp16 GEMM): Y[o][pt] = sum_c Wh[o][c] * Xt[pt][c]
// ---------------------------------------------------------------------------
__global__ __launch_bounds__(256) void proj_kernel() {
    extern __shared__ unsigned smu[];
    const int TSZ = 128 * SEW;
    const int STG = 2 * TSZ;
    int tid = threadIdx.x, lane = tid & 31, warp = tid >> 5;
    int g = lane >> 2, tig = lane & 3, wm = warp >> 2, wn = warp & 3;
    int bz = blockIdx.z, w = bz % 3, b = bz / 3;
    int m0 = blockIdx.y * 128, n0 = blockIdx.x * 128;
    const __half* Ap = g_Wh + (size_t)w * C_ * C_ + (size_t)m0 * C_;
    const __half* Bp = g_Xt + ((size_t)b * PT + n0) * C_;

    float acc[4][4][4]; ZERO_ACC(acc);
    const int NIT = C_ / 32;   // 8
    load_h(smu, Ap, C_, tid);            load_h(smu + TSZ, Bp, C_, tid);            cpc();
    load_h(smu + STG, Ap + 32, C_, tid); load_h(smu + STG + TSZ, Bp + 32, C_, tid); cpc();
    int sc = 0, sl = 2;
    for (int i = 0; i < NIT; i++) {
        cpw1(); __syncthreads();
        if (i + 2 < NIT) {
            load_h(smu + sl * STG, Ap + (i + 2) * 32, C_, tid);
            load_h(smu + sl * STG + TSZ, Bp + (i + 2) * 32, C_, tid);
        }
        cpc();
        unsigned Au = (unsigned)__cvta_generic_to_shared(smu + sc * STG);
        comp16(Au, Au + TSZ * 4, acc, wm, wn, lane);
        sc = (sc == 2) ? 0 : sc + 1; sl = (sl == 2) ? 0 : sl + 1;
    }

    if (w == 2) {
#pragma unroll
        for (int mi = 0; mi < 4; mi++)
#pragma unroll
            for (int half_ = 0; half_ < 2; half_++) {
                int o = m0 + wm * 64 + mi * 16 + g + half_ * 8;
                int h = o >> 5, d = o & 31;
                size_t base = ((size_t)(b * 8 + h)) * (P_ / 2);
#pragma unroll
                for (int ni = 0; ni < 4; ni++)
#pragma unroll
                    for (int e = 0; e < 2; e++) {
                        int col = n0 + wn * 32 + ni * 8 + 2 * tig + e;
                        int p = col >> 4, t = col & 15;
                        size_t idx = (base + (p >> 1)) * (size_t)(DT * 2) + (d * 16 + t) * 2 + (p & 1);
                        g_Vh[idx] = __float2half(acc[mi][ni][2 * half_ + e]);
                    }
            }
    } else {
        __half* dst = (w == 0) ? g_K : g_Q;
#pragma unroll
        for (int mi = 0; mi < 4; mi++)
#pragma unroll
            for (int half_ = 0; half_ < 2; half_++) {
                int o = m0 + wm * 64 + mi * 16 + g + half_ * 8;
                int h = o >> 5, d = o & 31;
                size_t base = ((size_t)(b * 8 + h)) * P_;
#pragma unroll
                for (int ni = 0; ni < 4; ni++) {
                    int col = n0 + wn * 32 + ni * 8 + 2 * tig;
                    int p = col >> 4, t = col & 15;
                    __half2 v = __floats2half2_rn(acc[mi][ni][2 * half_],
                                                  acc[mi][ni][2 * half_ + 1]);
                    *(__half2*)(dst + (base + p) * DT + d * 16 + t) = v;
                }
            }
    }
}

// ---------------------------------------------------------------------------
// energy: g_E[bh][q][p] = exp((sum_dt Q[q]·K[p])/sqrt(512)), 64-k chunks,
// fused per-block partial colsums -> g_Sp.
// ---------------------------------------------------------------------------
__global__ __launch_bounds__(256) void energy_kernel() {
    extern __shared__ unsigned smu[];
    const int TSZ = 128 * SE2;     // 4608 words
    const int STG = 2 * TSZ;
    int tid = threadIdx.x, lane = tid & 31, warp = tid >> 5;
    int g = lane >> 2, tig = lane & 3, wm = warp >> 2, wn = warp & 3;
    int bh = blockIdx.z, m0 = blockIdx.y * 128, n0 = blockIdx.x * 128;
    const __half* Ap = g_Q + (size_t)bh * P_ * DT + (size_t)m0 * DT;   // q rows
    const __half* Bp = g_K + (size_t)bh * P_ * DT + (size_t)n0 * DT;   // p rows

    float acc[4][4][4]; ZERO_ACC(acc);
    const int NIT = DT / 64;   // 8
    load_h64(smu, Ap, DT, tid);            load_h64(smu + TSZ, Bp, DT, tid);            cpc();
    load_h64(smu + STG, Ap + 64, DT, tid); load_h64(smu + STG + TSZ, Bp + 64, DT, tid); cpc();
    int sc = 0, sl = 2;
    for (int i = 0; i < NIT; i++) {
        cpw1(); __syncthreads();
        if (i + 2 < NIT) {
            load_h64(smu + sl * STG, Ap + (i + 2) * 64, DT, tid);
            load_h64(smu + sl * STG + TSZ, Bp + (i + 2) * 64, DT, tid);
        }
        cpc();
        unsigned Au = (unsigned)__cvta_generic_to_shared(smu + sc * STG);
        comp16_64(Au, Au + TSZ * 4, acc, wm, wn, lane);
        sc = (sc == 2) ? 0 : sc + 1; sl = (sl == 2) ? 0 : sl + 1;
    }

    __half* Ep = g_E + (size_t)bh * P_ * P_;
    float ps[4][2];
#pragma unroll
    for (int ni = 0; ni < 4; ni++) { ps[ni][0] = 0.f; ps[ni][1] = 0.f; }
#pragma unroll
    for (int mi = 0; mi < 4; mi++) {
        int q = m0 + wm * 64 + mi * 16 + g;
#pragma unroll
        for (int ni = 0; ni < 4; ni++) {
            int p = n0 + wn * 32 + ni * 8 + 2 * tig;
            float e0 = __expf(acc[mi][ni][0] * INVS), e1 = __expf(acc[mi][ni][1] * INVS);
            float e2 = __expf(acc[mi][ni][2] * INVS), e3 = __expf(acc[mi][ni][3] * INVS);
            *(__half2*)(Ep + (size_t)q * P_ + p)       = __floats2half2_rn(e0, e1);
            *(__half2*)(Ep + (size_t)(q + 8) * P_ + p) = __floats2half2_rn(e2, e3);
            ps[ni][0] += e0 + e2;
            ps[ni][1] += e1 + e3;
        }
    }
    // stage partial sums: [p_local 0..127][slot 0..15], stride 17
    __syncthreads();
    float* red = (float*)smu;
#pragma unroll
    for (int ni = 0; ni < 4; ni++)
#pragma unroll
        for (int e = 0; e < 2; e++) {
            int pl = wn * 32 + ni * 8 + 2 * tig + e;
            red[pl * 17 + wm * 8 + g] = ps[ni][e];
        }
    __syncthreads();
    if (tid < 128) {
        float s = 0.f;
#pragma unroll
        for (int k = 0; k < 16; k++) s += red[tid * 17 + k];
        g_Sp[((size_t)bh * 8 + blockIdx.y) * P_ + n0 + tid] = s;
    }
}

// ---------------------------------------------------------------------------
// sreduce: g_S[bh][p] = 1 / sum_m g_Sp[bh][m][p]
// ---------------------------------------------------------------------------
__global__ __launch_bounds__(1024) void sreduce_kernel() {
    int bh = blockIdx.x, p = threadIdx.x;
    float s = 0.f;
#pragma unroll
    for (int m = 0; m < 8; m++) s += g_Sp[((size_t)bh * 8 + m) * P_ + p];
    g_S[(size_t)bh * P_ + p] = 1.0f / s;
}

// ---------------------------------------------------------------------------
// vscale: V'[p][dt] *= invS[p]
// ---------------------------------------------------------------------------
__global__ __launch_bounds__(256) void vscale_kernel() {
    size_t id = (size_t)blockIdx.x * 256 + threadIdx.x;
    size_t bhpp = id >> 7;
    int within = (int)(id & 127);
    int bh = (int)(bhpp >> 9);
    int pp = (int)(bhpp & 511);
    float s0 = g_S[(size_t)bh * P_ + 2 * pp];
    float s1 = g_S[(size_t)bh * P_ + 2 * pp + 1];
    __half2 sc = __floats2half2_rn(s0, s1);
    uint4* ptr = (uint4*)g_Vh + bhpp * 128 + within;
    uint4 u = *ptr;
    __half2* hp = (__half2*)&u;
#pragma unroll
    for (int j = 0; j < 4; j++) hp[j] = __hmul2(hp[j], sc);
    *ptr = u;
}

// ---------------------------------------------------------------------------
// av: out[q][dt] = sum_p exp[q][p] V'[p][dt]   (fp16 mma, 64-k chunks, 3-stage)
// ---------------------------------------------------------------------------
__global__ __launch_bounds__(256) void av_kernel(float* __restrict__ out) {
    extern __shared__ unsigned smu[];
    const int ATSZ = 128 * SE2;   // 4608 words
    const int BTSZ = 32 * SBV;    // 4352 words
    const int STG = ATSZ + BTSZ;  // 8960 words
    int tid = threadIdx.x, lane = tid & 31, warp = tid >> 5;
    int g = lane >> 2, tig = lane & 3, wm = warp >> 2, wn = warp & 3;
    int bh = blockIdx.z, b = bh >> 3, h = bh & 7;
    int m0 = blockIdx.y * 128;   // q
    int n0 = blockIdx.x * 128;   // dt
    const __half* Ap = g_E + ((size_t)bh * P_ + m0) * P_;
    const __half* Bp = g_Vh + (size_t)bh * P_ * DT + (size_t)n0 * 2;

    float acc[4][4][4]; ZERO_ACC(acc);
    const int NIT = P_ / 64;   // 16
    load_h64(smu, Ap, P_, tid);            load_v64(smu + ATSZ, Bp, tid);                       cpc();
    load_h64(smu + STG, Ap + 64, P_, tid); load_v64(smu + STG + ATSZ, Bp + 32 * (DT * 2), tid); cpc();
    int sc = 0, sl = 2;
    for (int i = 0; i < NIT; i++) {
        cpw1(); __syncthreads();
        if (i + 2 < NIT) {
            load_h64(smu + sl * STG, Ap + (i + 2) * 64, P_, tid);
            load_v64(smu + sl * STG + ATSZ, Bp + (size_t)(i + 2) * 32 * (DT * 2), tid);
        }
        cpc();
        unsigned Au = (unsigned)__cvta_generic_to_shared(smu + sc * STG);
        comp_av64(Au, smu + sc * STG + ATSZ, acc, wm, wn, g, tig, lane);
        sc = (sc == 2) ? 0 : sc + 1; sl = (sl == 2) ? 0 : sl + 1;
    }

#pragma unroll
    for (int mi = 0; mi < 4; mi++)
#pragma unroll
        for (int half_ = 0; half_ < 2; half_++) {
            int q = m0 + wm * 64 + mi * 16 + g + half_ * 8;
#pragma unroll
            for (int ni = 0; ni < 4; ni++) {
                int n = n0 + wn * 32 + ni * 8 + 2 * tig;
                int d = n >> 4, t = n & 15;
                float2 v = make_float2(acc[mi][ni][2 * half_], acc[mi][ni][2 * half_ + 1]);
                *(float2*)(out + (((size_t)b * C_ + h * 32 + d) * P_ + q) * T_ + t) = v;
            }
        }
}

// ---------------------------------------------------------------------------
extern "C" void kernel_launch(void* const* d_in, const int* in_sizes, int n_in,
                              void* d_out, int out_size) {
    const float* x  = (const float*)d_in[0];
    const float* Wk = (const float*)d_in[1];
    const float* Wq = (const float*)d_in[2];
    const float* Wv = (const float*)d_in[3];
    float* out = (float*)d_out;

    const int SM_PJ = 3 * 2 * 128 * SEW * 4;              // 61440
    const int SM_EN = 3 * 2 * 128 * SE2 * 4;              // 110592
    const int SM_AV = 3 * (128 * SE2 + 32 * SBV) * 4;     // 107520
    cudaFuncSetAttribute(proj_kernel,   cudaFuncAttributeMaxDynamicSharedMemorySize, SM_PJ);
    cudaFuncSetAttribute(energy_kernel, cudaFuncAttributeMaxDynamicSharedMemorySize, SM_EN);
    cudaFuncSetAttribute(av_kernel,     cudaFuncAttributeMaxDynamicSharedMemorySize, SM_AV);

    xprep_kernel<<<dim3(PT / 256, 4, B_), 256>>>(x);
    wprep_kernel<<<dim3(C_ * C_ / 4 / 256, 3), 256>>>(Wk, Wq, Wv);
    proj_kernel<<<dim3(PT / 128, C_ / 128, 3 * B_), 256, SM_PJ>>>();
    energy_kernel<<<dim3(P_ / 128, P_ / 128, BH), 256, SM_EN>>>();
    sreduce_kernel<<<BH, 1024>>>();
    vscale_kernel<<<(BH * (P_ / 2) * DT / 4) / 256, 256>>>();
    av_kernel<<<dim3(DT / 128, P_ / 128, BH), 256, SM_AV>>>(out);
}

// round 16
// speedup vs baseline: 2.2372x; 1.0444x over previous
#include <cuda_runtime.h>
#include <cuda_fp16.h>
#include <cstdint>

#define B_  8
#define C_  256
#define P_  1024
#define T_  16
#define DT  512      // D*T
#define PT  16384    // P*T
#define BH  64

// Scratch
__device__ __half g_Xt[(size_t)B_ * PT * C_];   // [b][pt][c] fp16 (transposed x)
__device__ __half g_Wh[3 * C_ * C_];            // [w][o][c] fp16
__device__ __half g_K[(size_t)BH * P_ * DT];    // [bh][p][dt] fp16
__device__ __half g_Q[(size_t)BH * P_ * DT];    // [bh][p][dt] fp16
__device__ __half g_Vh[(size_t)BH * P_ * DT];   // [bh][p/2][dt][2] fp16 (p-pair interleaved)
__device__ __half g_E[(size_t)BH * P_ * P_];    // [bh][q][p] fp16 = exp(energy/sqrt(512))
__device__ float  g_Sp[(size_t)BH * 8 * P_];    // per-mblock partial colsums
__device__ float  g_S[(size_t)BH * P_];         // 1/colsum

#define SEW 20    // (legacy) 32-half row stride (words)
#define SE2 36    // 64-half row stride: 128 rows x 64 halfs (words)
#define SBV 136   // av B tile word stride (kpair rows x 128 dt-words)
#define SET 136   // energy epilogue staging stride (halfs)
#define NTHR 256
#define INVS 0.044194173824159216f   // 1/sqrt(512)

__device__ __forceinline__ void mmah(float* c, unsigned a0, unsigned a1, unsigned a2, unsigned a3,
                                     unsigned b0, unsigned b1) {
    asm volatile(
        "mma.sync.aligned.m16n8k16.row.col.f32.f16.f16.f32 "
        "{%0,%1,%2,%3},{%4,%5,%6,%7},{%8,%9},{%0,%1,%2,%3};"
        : "+f"(c[0]), "+f"(c[1]), "+f"(c[2]), "+f"(c[3])
        : "r"(a0), "r"(a1), "r"(a2), "r"(a3), "r"(b0), "r"(b1));
}
__device__ __forceinline__ void ldsm4(unsigned& r0, unsigned& r1, unsigned& r2, unsigned& r3,
                                      unsigned addr) {
    asm volatile("ldmatrix.sync.aligned.m8n8.x4.shared.b16 {%0,%1,%2,%3}, [%4];"
        : "=r"(r0), "=r"(r1), "=r"(r2), "=r"(r3) : "r"(addr));
}
__device__ __forceinline__ void cp16(void* s, const void* g) {
    unsigned a = (unsigned)__cvta_generic_to_shared(s);
    asm volatile("cp.async.cg.shared.global [%0], [%1], 16;" :: "r"(a), "l"(g));
}
__device__ __forceinline__ void cpc()  { asm volatile("cp.async.commit_group;"); }
__device__ __forceinline__ void cpw1() { asm volatile("cp.async.wait_group 1;"); }

// ---- tile loaders ----
// 128 rows x 64 halfs, stride SE2
__device__ __forceinline__ void load_h64(unsigned* buf, const void* gv, int ldg, int tid) {
    const __half* g = (const __half*)gv;
#pragma unroll
    for (int j = 0; j < 4; j++) {
        int c = tid + j * NTHR;
        int row = c >> 3, ch = c & 7;
        cp16(buf + row * SE2 + ch * 4, g + (size_t)row * ldg + ch * 8);
    }
}
// av B: 32 kpair rows x 512B, gmem row stride DT*2 halfs
__device__ __forceinline__ void load_v64(unsigned* buf, const __half* g, int tid) {
#pragma unroll
    for (int j = 0; j < 4; j++) {
        int c = tid + j * NTHR;
        int row = c >> 5, ch = c & 31;
        cp16(buf + row * SBV + ch * 4, g + (size_t)row * (DT * 2) + ch * 8);
    }
}

// ---- fp16 GEMM compute (64-k chunk, stride SE2, both operands ldmatrix) ----
__device__ __forceinline__ void comp16_64(unsigned Au, unsigned Bu, float acc[4][4][4],
                                          int wm, int wn, int lane) {
    unsigned aBase = Au + (unsigned)((wm * 64 + (lane & 15)) * SE2 * 4) + ((lane & 16) ? 16u : 0u);
    unsigned bBase = Bu + (unsigned)((wn * 32 + (lane & 7) + ((lane >> 4) << 3)) * SE2 * 4)
                       + ((lane & 8) ? 16u : 0u);
#pragma unroll
    for (int c = 0; c < 4; c++) {
        unsigned co = c * 32;
        unsigned bb[4][2];
        ldsm4(bb[0][0], bb[0][1], bb[1][0], bb[1][1], bBase + co);
        ldsm4(bb[2][0], bb[2][1], bb[3][0], bb[3][1], bBase + 16 * SE2 * 4 + co);
#pragma unroll
        for (int mi = 0; mi < 4; mi++) {
            unsigned a0, a1, a2, a3;
            ldsm4(a0, a1, a2, a3, aBase + mi * (16 * SE2 * 4) + co);
#pragma unroll
            for (int ni = 0; ni < 4; ni++)
                mmah(acc[mi][ni], a0, a1, a2, a3, bb[ni][0], bb[ni][1]);
        }
    }
}

// ---- av compute (64-k chunk): A ldmatrix (stride SE2), B scalar kpair-major ----
__device__ __forceinline__ void comp_av64(unsigned Au, const unsigned* Bt, float acc[4][4][4],
                                          int wm, int wn, int g, int tig, int lane) {
    unsigned aBase = Au + (unsigned)((wm * 64 + (lane & 15)) * SE2 * 4) + ((lane & 16) ? 16u : 0u);
#pragma unroll
    for (int c = 0; c < 4; c++) {
        int w0 = c * 8 + tig;
        unsigned bb[4][2];
#pragma unroll
        for (int ni = 0; ni < 4; ni++) {
            int n = wn * 32 + ni * 8 + g;
            bb[ni][0] = Bt[w0 * SBV + n]; bb[ni][1] = Bt[(w0 + 4) * SBV + n];
        }
#pragma unroll
        for (int mi = 0; mi < 4; mi++) {
            unsigned a0, a1, a2, a3;
            ldsm4(a0, a1, a2, a3, aBase + mi * (16 * SE2 * 4) + c * 32);
#pragma unroll
            for (int ni = 0; ni < 4; ni++)
                mmah(acc[mi][ni], a0, a1, a2, a3, bb[ni][0], bb[ni][1]);
        }
    }
}

#define ZERO_ACC(acc) \
    _Pragma("unroll") for (int mi = 0; mi < 4; mi++) \
    _Pragma("unroll") for (int ni = 0; ni < 4; ni++) \
    _Pragma("unroll") for (int e = 0; e < 4; e++) acc[mi][ni][e] = 0.f;

// ---------------------------------------------------------------------------
// xprep: g_Xt[b][pt][c] = fp16(x[b][c][pt])
// ---------------------------------------------------------------------------
__global__ __launch_bounds__(256) void xprep_kernel(const float* __restrict__ x) {
    int b = blockIdx.z, c0 = blockIdx.y * 64;
    int pt = blockIdx.x * 256 + threadIdx.x;
    const float* xp = x + ((size_t)b * C_ + c0) * PT + pt;
    __half h[64];
#pragma unroll
    for (int c = 0; c < 64; c++) h[c] = __float2half(xp[(size_t)c * PT]);
    __half* dst = g_Xt + ((size_t)b * PT + pt) * C_ + c0;
#pragma unroll
    for (int j = 0; j < 8; j++) ((uint4*)dst)[j] = ((const uint4*)h)[j];
}

// ---------------------------------------------------------------------------
// wprep: g_Wh[w][o][c] = fp16(W[o][c])
// ---------------------------------------------------------------------------
__global__ __launch_bounds__(256) void wprep_kernel(const float* __restrict__ Wk,
                                                    const float* __restrict__ Wq,
                                                    const float* __restrict__ Wv) {
    int w = blockIdx.y;
    const float* src = (w == 0) ? Wk : (w == 1) ? Wq : Wv;
    int id = blockIdx.x * 256 + threadIdx.x;
    float4 v = ((const float4*)src)[id];
    __half h[4] = {__float2half(v.x), __float2half(v.y), __float2half(v.z), __float2half(v.w)};
    ((uint2*)(g_Wh + (size_t)w * C_ * C_))[id] = *(const uint2*)h;
}

// ---------------------------------------------------------------------------
// proj (fp16 GEMM, 64-k chunks): Y[o][pt] = sum_c Wh[o][c] * Xt[pt][c]
// ---------------------------------------------------------------------------
__global__ __launch_bounds__(256) void proj_kernel() {
    extern __shared__ unsigned smu[];
    const int TSZ = 128 * SE2;     // 4608 words
    const int STG = 2 * TSZ;
    int tid = threadIdx.x, lane = tid & 31, warp = tid >> 5;
    int g = lane >> 2, tig = lane & 3, wm = warp >> 2, wn = warp & 3;
    int bz = blockIdx.z, w = bz % 3, b = bz / 3;
    int m0 = blockIdx.y * 128, n0 = blockIdx.x * 128;
    const __half* Ap = g_Wh + (size_t)w * C_ * C_ + (size_t)m0 * C_;
    const __half* Bp = g_Xt + ((size_t)b * PT + n0) * C_;

    float acc[4][4][4]; ZERO_ACC(acc);
    const int NIT = C_ / 64;   // 4
    load_h64(smu, Ap, C_, tid);            load_h64(smu + TSZ, Bp, C_, tid);            cpc();
    load_h64(smu + STG, Ap + 64, C_, tid); load_h64(smu + STG + TSZ, Bp + 64, C_, tid); cpc();
    int sc = 0, sl = 2;
    for (int i = 0; i < NIT; i++) {
        cpw1(); __syncthreads();
        if (i + 2 < NIT) {
            load_h64(smu + sl * STG, Ap + (i + 2) * 64, C_, tid);
            load_h64(smu + sl * STG + TSZ, Bp + (i + 2) * 64, C_, tid);
        }
        cpc();
        unsigned Au = (unsigned)__cvta_generic_to_shared(smu + sc * STG);
        comp16_64(Au, Au + TSZ * 4, acc, wm, wn, lane);
        sc = (sc == 2) ? 0 : sc + 1; sl = (sl == 2) ? 0 : sl + 1;
    }

    if (w == 2) {
#pragma unroll
        for (int mi = 0; mi < 4; mi++)
#pragma unroll
            for (int half_ = 0; half_ < 2; half_++) {
                int o = m0 + wm * 64 + mi * 16 + g + half_ * 8;
                int h = o >> 5, d = o & 31;
                size_t base = ((size_t)(b * 8 + h)) * (P_ / 2);
#pragma unroll
                for (int ni = 0; ni < 4; ni++)
#pragma unroll
                    for (int e = 0; e < 2; e++) {
                        int col = n0 + wn * 32 + ni * 8 + 2 * tig + e;
                        int p = col >> 4, t = col & 15;
                        size_t idx = (base + (p >> 1)) * (size_t)(DT * 2) + (d * 16 + t) * 2 + (p & 1);
                        g_Vh[idx] = __float2half(acc[mi][ni][2 * half_ + e]);
                    }
            }
    } else {
        __half* dst = (w == 0) ? g_K : g_Q;
#pragma unroll
        for (int mi = 0; mi < 4; mi++)
#pragma unroll
            for (int half_ = 0; half_ < 2; half_++) {
                int o = m0 + wm * 64 + mi * 16 + g + half_ * 8;
                int h = o >> 5, d = o & 31;
                size_t base = ((size_t)(b * 8 + h)) * P_;
#pragma unroll
                for (int ni = 0; ni < 4; ni++) {
                    int col = n0 + wn * 32 + ni * 8 + 2 * tig;
                    int p = col >> 4, t = col & 15;
                    __half2 v = __floats2half2_rn(acc[mi][ni][2 * half_],
                                                  acc[mi][ni][2 * half_ + 1]);
                    *(__half2*)(dst + (base + p) * DT + d * 16 + t) = v;
                }
            }
    }
}

// ---------------------------------------------------------------------------
// energy: g_E[bh][q][p] = exp((sum_dt Q[q]·K[p])/sqrt(512)), 64-k chunks,
// smem-staged coalesced E writes + fused per-block partial colsums.
// ---------------------------------------------------------------------------
__global__ __launch_bounds__(256) void energy_kernel() {
    extern __shared__ unsigned smu[];
    const int TSZ = 128 * SE2;     // 4608 words
    const int STG = 2 * TSZ;
    int tid = threadIdx.x, lane = tid & 31, warp = tid >> 5;
    int g = lane >> 2, tig = lane & 3, wm = warp >> 2, wn = warp & 3;
    int bh = blockIdx.z, m0 = blockIdx.y * 128, n0 = blockIdx.x * 128;
    const __half* Ap = g_Q + (size_t)bh * P_ * DT + (size_t)m0 * DT;   // q rows
    const __half* Bp = g_K + (size_t)bh * P_ * DT + (size_t)n0 * DT;   // p rows

    float acc[4][4][4]; ZERO_ACC(acc);
    const int NIT = DT / 64;   // 8
    load_h64(smu, Ap, DT, tid);            load_h64(smu + TSZ, Bp, DT, tid);            cpc();
    load_h64(smu + STG, Ap + 64, DT, tid); load_h64(smu + STG + TSZ, Bp + 64, DT, tid); cpc();
    int sc = 0, sl = 2;
    for (int i = 0; i < NIT; i++) {
        cpw1(); __syncthreads();
        if (i + 2 < NIT) {
            load_h64(smu + sl * STG, Ap + (i + 2) * 64, DT, tid);
            load_h64(smu + sl * STG + TSZ, Bp + (i + 2) * 64, DT, tid);
        }
        cpc();
        unsigned Au = (unsigned)__cvta_generic_to_shared(smu + sc * STG);
        comp16_64(Au, Au + TSZ * 4, acc, wm, wn, lane);
        sc = (sc == 2) ? 0 : sc + 1; sl = (sl == 2) ? 0 : sl + 1;
    }

    // epilogue: exp + stage into smem tile [128q][SET halfs], accumulate partial colsums
    __syncthreads();
    __half* et = (__half*)smu;
    float ps[4][2];
#pragma unroll
    for (int ni = 0; ni < 4; ni++) { ps[ni][0] = 0.f; ps[ni][1] = 0.f; }
#pragma unroll
    for (int mi = 0; mi < 4; mi++) {
        int ql = wm * 64 + mi * 16 + g;
#pragma unroll
        for (int ni = 0; ni < 4; ni++) {
            int pl = wn * 32 + ni * 8 + 2 * tig;
            float e0 = __expf(acc[mi][ni][0] * INVS), e1 = __expf(acc[mi][ni][1] * INVS);
            float e2 = __expf(acc[mi][ni][2] * INVS), e3 = __expf(acc[mi][ni][3] * INVS);
            *(__half2*)(et + ql * SET + pl)       = __floats2half2_rn(e0, e1);
            *(__half2*)(et + (ql + 8) * SET + pl) = __floats2half2_rn(e2, e3);
            ps[ni][0] += e0 + e2;
            ps[ni][1] += e1 + e3;
        }
    }
    __syncthreads();
    // coalesced tile write: 128 rows x 16 uint4
    {
        __half* Ep = g_E + ((size_t)bh * P_ + m0) * P_ + n0;
#pragma unroll
        for (int j = 0; j < 8; j++) {
            int s = tid + j * 256;
            int row = s >> 4, c16 = s & 15;
            *(uint4*)(Ep + (size_t)row * P_ + c16 * 8) = *(const uint4*)(et + row * SET + c16 * 8);
        }
    }
    __syncthreads();
    // stage partial sums: [p_local 0..127][slot 0..15], stride 17
    float* red = (float*)smu;
#pragma unroll
    for (int ni = 0; ni < 4; ni++)
#pragma unroll
        for (int e = 0; e < 2; e++) {
            int pl = wn * 32 + ni * 8 + 2 * tig + e;
            red[pl * 17 + wm * 8 + g] = ps[ni][e];
        }
    __syncthreads();
    if (tid < 128) {
        float s = 0.f;
#pragma unroll
        for (int k = 0; k < 16; k++) s += red[tid * 17 + k];
        g_Sp[((size_t)bh * 8 + blockIdx.y) * P_ + n0 + tid] = s;
    }
}

// ---------------------------------------------------------------------------
// sreduce: g_S[bh][p] = 1 / sum_m g_Sp[bh][m][p]
// ---------------------------------------------------------------------------
__global__ __launch_bounds__(1024) void sreduce_kernel() {
    int bh = blockIdx.x, p = threadIdx.x;
    float s = 0.f;
#pragma unroll
    for (int m = 0; m < 8; m++) s += g_Sp[((size_t)bh * 8 + m) * P_ + p];
    g_S[(size_t)bh * P_ + p] = 1.0f / s;
}

// ---------------------------------------------------------------------------
// vscale: V'[p][dt] *= invS[p]
// ---------------------------------------------------------------------------
__global__ __launch_bounds__(256) void vscale_kernel() {
    size_t id = (size_t)blockIdx.x * 256 + threadIdx.x;
    size_t bhpp = id >> 7;
    int within = (int)(id & 127);
    int bh = (int)(bhpp >> 9);
    int pp = (int)(bhpp & 511);
    float s0 = g_S[(size_t)bh * P_ + 2 * pp];
    float s1 = g_S[(size_t)bh * P_ + 2 * pp + 1];
    __half2 sc = __floats2half2_rn(s0, s1);
    uint4* ptr = (uint4*)g_Vh + bhpp * 128 + within;
    uint4 u = *ptr;
    __half2* hp = (__half2*)&u;
#pragma unroll
    for (int j = 0; j < 4; j++) hp[j] = __hmul2(hp[j], sc);
    *ptr = u;
}

// ---------------------------------------------------------------------------
// av: out[q][dt] = sum_p exp[q][p] V'[p][dt]   (fp16 mma, 64-k chunks, 3-stage)
// ---------------------------------------------------------------------------
__global__ __launch_bounds__(256) void av_kernel(float* __restrict__ out) {
    extern __shared__ unsigned smu[];
    const int ATSZ = 128 * SE2;   // 4608 words
    const int BTSZ = 32 * SBV;    // 4352 words
    const int STG = ATSZ + BTSZ;  // 8960 words
    int tid = threadIdx.x, lane = tid & 31, warp = tid >> 5;
    int g = lane >> 2, tig = lane & 3, wm = warp >> 2, wn = warp & 3;
    int bh = blockIdx.z, b = bh >> 3, h = bh & 7;
    int m0 = blockIdx.y * 128;   // q
    int n0 = blockIdx.x * 128;   // dt
    const __half* Ap = g_E + ((size_t)bh * P_ + m0) * P_;
    const __half* Bp = g_Vh + (size_t)bh * P_ * DT + (size_t)n0 * 2;

    float acc[4][4][4]; ZERO_ACC(acc);
    const int NIT = P_ / 64;   // 16
    load_h64(smu, Ap, P_, tid);            load_v64(smu + ATSZ, Bp, tid);                       cpc();
    load_h64(smu + STG, Ap + 64, P_, tid); load_v64(smu + STG + ATSZ, Bp + 32 * (DT * 2), tid); cpc();
    int sc = 0, sl = 2;
    for (int i = 0; i < NIT; i++) {
        cpw1(); __syncthreads();
        if (i + 2 < NIT) {
            load_h64(smu + sl * STG, Ap + (i + 2) * 64, P_, tid);
            load_v64(smu + sl * STG + ATSZ, Bp + (size_t)(i + 2) * 32 * (DT * 2), tid);
        }
        cpc();
        unsigned Au = (unsigned)__cvta_generic_to_shared(smu + sc * STG);
        comp_av64(Au, smu + sc * STG + ATSZ, acc, wm, wn, g, tig, lane);
        sc = (sc == 2) ? 0 : sc + 1; sl = (sl == 2) ? 0 : sl + 1;
    }

#pragma unroll
    for (int mi = 0; mi < 4; mi++)
#pragma unroll
        for (int half_ = 0; half_ < 2; half_++) {
            int q = m0 + wm * 64 + mi * 16 + g + half_ * 8;
#pragma unroll
            for (int ni = 0; ni < 4; ni++) {
                int n = n0 + wn * 32 + ni * 8 + 2 * tig;
                int d = n >> 4, t = n & 15;
                float2 v = make_float2(acc[mi][ni][2 * half_], acc[mi][ni][2 * half_ + 1]);
                *(float2*)(out + (((size_t)b * C_ + h * 32 + d) * P_ + q) * T_ + t) = v;
            }
        }
}

// ---------------------------------------------------------------------------
extern "C" void kernel_launch(void* const* d_in, const int* in_sizes, int n_in,
                              void* d_out, int out_size) {
    const float* x  = (const float*)d_in[0];
    const float* Wk = (const float*)d_in[1];
    const float* Wq = (const float*)d_in[2];
    const float* Wv = (const float*)d_in[3];
    float* out = (float*)d_out;

    const int SM_PJ = 3 * 2 * 128 * SE2 * 4;              // 110592
    const int SM_EN = 3 * 2 * 128 * SE2 * 4;              // 110592
    const int SM_AV = 3 * (128 * SE2 + 32 * SBV) * 4;     // 107520
    cudaFuncSetAttribute(proj_kernel,   cudaFuncAttributeMaxDynamicSharedMemorySize, SM_PJ);
    cudaFuncSetAttribute(energy_kernel, cudaFuncAttributeMaxDynamicSharedMemorySize, SM_EN);
    cudaFuncSetAttribute(av_kernel,     cudaFuncAttributeMaxDynamicSharedMemorySize, SM_AV);

    xprep_kernel<<<dim3(PT / 256, 4, B_), 256>>>(x);
    wprep_kernel<<<dim3(C_ * C_ / 4 / 256, 3), 256>>>(Wk, Wq, Wv);
    proj_kernel<<<dim3(PT / 128, C_ / 128, 3 * B_), 256, SM_PJ>>>();
    energy_kernel<<<dim3(P_ / 128, P_ / 128, BH), 256, SM_EN>>>();
    sreduce_kernel<<<BH, 1024>>>();
    vscale_kernel<<<(BH * (P_ / 2) * DT / 4) / 256, 256>>>();
    av_kernel<<<dim3(DT / 128, P_ / 128, BH), 256, SM_AV>>>(out);
}